// round 2
// baseline (speedup 1.0000x reference)
#include <cuda_runtime.h>

// Problem constants (shapes fixed by setup_inputs)
#define NMAX 50000
#define EMAX 800000
#define DD   128
#define RR   8
#define TTY  4

// ---------------- device scratch (no allocations allowed) ----------------
__device__ float g_y [(size_t)NMAX * DD];           // 25.6 MB  (y1, then y2)
__device__ float g_h [(size_t)RR * NMAX * DD];      // 204.8 MB (per-relation transformed feats)
__device__ float g_x1[(size_t)NMAX * DD];           // 25.6 MB  (x after conv residual)
__device__ int   g_deg[NMAX + 1];
__device__ int   g_off[NMAX + 1];
__device__ int   g_cur[NMAX];
__device__ int   g_ebuf[EMAX];                      // packed (edge_type<<16)|src
__device__ int   g_tcnt[TTY], g_toff[TTY], g_tcur[TTY];
__device__ int   g_perm[NMAX];                      // node ids grouped by type

// ---------------- small kernels ----------------

__global__ void zero_kernel(int N) {
    int i = blockIdx.x * blockDim.x + threadIdx.x;
    if (i < N) g_deg[i] = 0;
    if (i < TTY) g_tcnt[i] = 0;
}

// LayerNorm (per-node-type affine) + ReLU. One warp per node.
__global__ void ln_relu_kernel(const float* __restrict__ xin,
                               const int*   __restrict__ ntype,
                               const float* __restrict__ gamma,
                               const float* __restrict__ beta,
                               int N, int use_internal, int count_types) {
    int gwarp = (blockIdx.x * blockDim.x + threadIdx.x) >> 5;
    int lane  = threadIdx.x & 31;
    if (gwarp >= N) return;
    const float* src = use_internal ? g_x1 : xin;
    const float4* xr = (const float4*)(src + (size_t)gwarp * DD);
    float4 v = xr[lane];
    float s  = v.x + v.y + v.z + v.w;
    float sq = v.x*v.x + v.y*v.y + v.z*v.z + v.w*v.w;
    #pragma unroll
    for (int d = 16; d; d >>= 1) {
        s  += __shfl_xor_sync(0xFFFFFFFFu, s,  d);
        sq += __shfl_xor_sync(0xFFFFFFFFu, sq, d);
    }
    float mu  = s * (1.0f / DD);
    float var = sq * (1.0f / DD) - mu * mu;
    float rs  = rsqrtf(var + 1e-5f);
    int t = ntype[gwarp];
    float4 g = ((const float4*)(gamma + (size_t)t * DD))[lane];
    float4 b = ((const float4*)(beta  + (size_t)t * DD))[lane];
    float4 o;
    o.x = fmaxf((v.x - mu) * rs * g.x + b.x, 0.0f);
    o.y = fmaxf((v.y - mu) * rs * g.y + b.y, 0.0f);
    o.z = fmaxf((v.z - mu) * rs * g.z + b.z, 0.0f);
    o.w = fmaxf((v.w - mu) * rs * g.w + b.w, 0.0f);
    ((float4*)(g_y + (size_t)gwarp * DD))[lane] = o;
    if (count_types && lane == 0) atomicAdd(&g_tcnt[t], 1);
}

__global__ void count_edges_kernel(const int* __restrict__ edst, int E) {
    int i = blockIdx.x * blockDim.x + threadIdx.x;
    if (i < E) atomicAdd(&g_deg[edst[i]], 1);
}

// Single-block exclusive scan of g_deg -> g_off/g_cur; also scans g_tcnt.
__global__ void scan_kernel(int N, int E) {
    const int TH = 256;
    __shared__ int warpsum[8];
    int t = threadIdx.x;
    int CH = (N + TH - 1) / TH;
    int s0 = t * CH;
    int s1 = min(s0 + CH, N);
    int s = 0;
    for (int i = s0; i < s1; i++) s += g_deg[i];
    // inclusive warp scan
    int v = s;
    #pragma unroll
    for (int d = 1; d < 32; d <<= 1) {
        int n = __shfl_up_sync(0xFFFFFFFFu, v, d);
        if ((t & 31) >= d) v += n;
    }
    if ((t & 31) == 31) warpsum[t >> 5] = v;
    __syncthreads();
    if (t == 0) {
        int r = 0;
        #pragma unroll
        for (int w = 0; w < 8; w++) { int x = warpsum[w]; warpsum[w] = r; r += x; }
    }
    __syncthreads();
    int excl = v - s + warpsum[t >> 5];
    int run = excl;
    for (int i = s0; i < s1; i++) {
        g_off[i] = run;
        g_cur[i] = run;
        run += g_deg[i];
    }
    if (t == TH - 1) g_off[N] = run;   // == E
    if (t == 0) {
        int r = 0;
        #pragma unroll
        for (int tt = 0; tt < TTY; tt++) {
            g_toff[tt] = r; g_tcur[tt] = r; r += g_tcnt[tt];
        }
    }
}

__global__ void scatter_edges_kernel(const int* __restrict__ esrc,
                                     const int* __restrict__ edst,
                                     const int* __restrict__ etype, int E) {
    int i = blockIdx.x * blockDim.x + threadIdx.x;
    if (i < E) {
        int p = atomicAdd(&g_cur[edst[i]], 1);
        g_ebuf[p] = (etype[i] << 16) | esrc[i];
    }
}

__global__ void scatter_perm_kernel(const int* __restrict__ ntype, int N) {
    int i = blockIdx.x * blockDim.x + threadIdx.x;
    if (i < N) {
        int t = ntype[i];
        int p = atomicAdd(&g_tcur[t], 1);
        g_perm[p] = i;
    }
}

// Per-dst aggregation: x1[j] += sum over incident edges of H[et][src].
// One block of 128 threads per node; no floating-point atomics.
__global__ void agg_kernel(int N) {
    int j = blockIdx.x;
    int d = threadIdx.x;
    int beg = g_off[j], end = g_off[j + 1];
    float acc = g_x1[(size_t)j * DD + d];
    for (int k = beg; k < end; k++) {
        int p = g_ebuf[k];
        int src = p & 0xFFFF;
        int et  = p >> 16;
        acc += g_h[((size_t)et * N + src) * DD + d];
    }
    g_x1[(size_t)j * DD + d] = acc;
}

// ---------------- 128x128x16-tile fp32 GEMM ----------------
// C[M,128] = A[M,128] @ B[128,128] (+ epilogue)
// MODE 0: H GEMM.  blockIdx.y = relation r.  A=g_y, B=Bp+r*D*D, C=g_h+r*M*D.
// MODE 1: root.    A=g_y, B=Bp, C=g_x1, C += ADDp (the original x).
// MODE 2: MLP.     blockIdx.y = type t. rows via g_perm bucket; A=g_y,
//                  B=Bp+t*D*D, C=Cp (d_out), += g_x1 row + bias.
template<int MODE>
__global__ __launch_bounds__(256, 2)
void gemm128_kernel(const float* __restrict__ Bp,
                    const float* __restrict__ ADDp,
                    const float* __restrict__ biasp,
                    float* __restrict__ Cp,
                    int M) {
    __shared__ float As[16][DD];
    __shared__ float Bs[16][DD];

    const int tid = threadIdx.x;
    const int sel = blockIdx.y;

    const float* A = g_y;
    const float* B;
    float* C;
    const float* ADD = nullptr;
    const float* bias = nullptr;
    const int* perm = nullptr;
    int Mloc = M;

    if (MODE == 0) {
        B = Bp + (size_t)sel * DD * DD;
        C = g_h + (size_t)sel * M * DD;
    } else if (MODE == 1) {
        B = Bp;
        C = g_x1;
        ADD = ADDp;
    } else {
        B = Bp + (size_t)sel * DD * DD;
        bias = biasp + (size_t)sel * DD;
        C = Cp;
        ADD = g_x1;
        Mloc = g_tcnt[sel];
        perm = g_perm + g_toff[sel];
    }

    const int m0 = blockIdx.x * 128;
    if (m0 >= Mloc) return;

    const int tx = tid & 15;        // 0..15
    const int ty = tid >> 4;        // 0..15
    const int tx4 = tx * 4;
    const int ty4 = ty * 4;

    float c[8][8];
    #pragma unroll
    for (int i = 0; i < 8; i++)
        #pragma unroll
        for (int j = 0; j < 8; j++) c[i][j] = 0.0f;

    // A tile loader mapping: thread -> (row 0..63, colgroup 0..3), 2 row passes
    const int lrow = tid >> 2;
    const int lcg  = (tid & 3) * 4;
    // B tile loader mapping: (krow 0..7, col group), 2 krow passes
    const int brow = tid >> 5;
    const int bcol = (tid & 31) * 4;

    const int gr0 = m0 + lrow;
    const int gr1 = m0 + lrow + 64;
    const bool v0 = gr0 < Mloc;
    const bool v1 = gr1 < Mloc;
    int ar0 = 0, ar1 = 0;
    if (MODE == 2) {
        if (v0) ar0 = perm[gr0];
        if (v1) ar1 = perm[gr1];
    } else {
        ar0 = gr0; ar1 = gr1;
    }

    for (int kt = 0; kt < 8; kt++) {
        const int kb = kt * 16;
        float4 a0 = make_float4(0, 0, 0, 0), a1 = make_float4(0, 0, 0, 0);
        if (v0) a0 = *(const float4*)&A[(size_t)ar0 * DD + kb + lcg];
        if (v1) a1 = *(const float4*)&A[(size_t)ar1 * DD + kb + lcg];
        float4 b0 = *(const float4*)&B[(size_t)(kb + brow) * DD + bcol];
        float4 b1 = *(const float4*)&B[(size_t)(kb + brow + 8) * DD + bcol];

        __syncthreads();
        As[lcg + 0][lrow] = a0.x; As[lcg + 1][lrow] = a0.y;
        As[lcg + 2][lrow] = a0.z; As[lcg + 3][lrow] = a0.w;
        As[lcg + 0][lrow + 64] = a1.x; As[lcg + 1][lrow + 64] = a1.y;
        As[lcg + 2][lrow + 64] = a1.z; As[lcg + 3][lrow + 64] = a1.w;
        *(float4*)&Bs[brow][bcol]     = b0;
        *(float4*)&Bs[brow + 8][bcol] = b1;
        __syncthreads();

        #pragma unroll
        for (int kk = 0; kk < 16; kk++) {
            float4 aa0 = *(const float4*)&As[kk][ty4];
            float4 aa1 = *(const float4*)&As[kk][ty4 + 64];
            float4 bb0 = *(const float4*)&Bs[kk][tx4];
            float4 bb1 = *(const float4*)&Bs[kk][tx4 + 64];
            float av[8] = {aa0.x, aa0.y, aa0.z, aa0.w, aa1.x, aa1.y, aa1.z, aa1.w};
            float bv[8] = {bb0.x, bb0.y, bb0.z, bb0.w, bb1.x, bb1.y, bb1.z, bb1.w};
            #pragma unroll
            for (int i = 0; i < 8; i++)
                #pragma unroll
                for (int j = 0; j < 8; j++)
                    c[i][j] += av[i] * bv[j];
        }
    }

    // epilogue
    #pragma unroll
    for (int i = 0; i < 8; i++) {
        const int rl = (i < 4) ? (ty4 + i) : (64 + ty4 + i - 4);
        const int gr = m0 + rl;
        if (gr >= Mloc) continue;
        const int prow = (MODE == 2) ? perm[gr] : gr;
        const size_t base = (size_t)prow * DD;
        #pragma unroll
        for (int h = 0; h < 2; h++) {
            const int n = h * 64 + tx4;
            float4 o = make_float4(c[i][h*4+0], c[i][h*4+1], c[i][h*4+2], c[i][h*4+3]);
            if (MODE >= 1) {
                float4 av = *(const float4*)&ADD[base + n];
                o.x += av.x; o.y += av.y; o.z += av.z; o.w += av.w;
            }
            if (MODE == 2) {
                float4 bvv = *(const float4*)&bias[n];
                o.x += bvv.x; o.y += bvv.y; o.z += bvv.z; o.w += bvv.w;
            }
            *(float4*)&C[base + n] = o;
        }
    }
}

// ---------------- host launcher ----------------
extern "C" void kernel_launch(void* const* d_in, const int* in_sizes, int n_in,
                              void* d_out, int out_size) {
    const float* x          = (const float*)d_in[0];
    const int*   edge_src   = (const int*)  d_in[1];
    const int*   edge_dst   = (const int*)  d_in[2];
    const int*   node_type  = (const int*)  d_in[3];
    const int*   edge_type  = (const int*)  d_in[4];
    const float* conv_gamma = (const float*)d_in[5];
    const float* conv_beta  = (const float*)d_in[6];
    const float* W_rel      = (const float*)d_in[7];
    const float* W_root     = (const float*)d_in[8];
    const float* mlp_gamma  = (const float*)d_in[9];
    const float* mlp_beta   = (const float*)d_in[10];
    const float* W_mlp      = (const float*)d_in[11];
    const float* b_mlp      = (const float*)d_in[12];
    float* out = (float*)d_out;

    const int N = in_sizes[0] / DD;
    const int E = in_sizes[1];

    const int THR = 256;
    dim3 blk(THR);

    // 0) zero counters
    zero_kernel<<<(N + THR - 1) / THR, blk>>>(N);

    // 1) y1 = relu(LN(x)) with conv affine; also count node types
    {
        int blocks = (N + 7) / 8;   // 8 warps per block
        ln_relu_kernel<<<blocks, blk>>>(x, node_type, conv_gamma, conv_beta, N, 0, 1);
    }

    // 2) CSR build part 1: degree histogram
    count_edges_kernel<<<(E + THR - 1) / THR, blk>>>(edge_dst, E);

    // 3) scan -> offsets (also type offsets)
    scan_kernel<<<1, THR>>>(N, E);

    // 4) scatter edges into CSR; scatter node ids into type buckets
    scatter_edges_kernel<<<(E + THR - 1) / THR, blk>>>(edge_src, edge_dst, edge_type, E);
    scatter_perm_kernel<<<(N + THR - 1) / THR, blk>>>(node_type, N);

    const int gx = (N + 127) / 128;

    // 5) H_r = y1 @ W_rel[r]  (8 GEMMs)
    gemm128_kernel<0><<<dim3(gx, RR), blk>>>(W_rel, nullptr, nullptr, nullptr, N);

    // 6) x1 = x + y1 @ W_root
    gemm128_kernel<1><<<dim3(gx, 1), blk>>>(W_root, x, nullptr, nullptr, N);

    // 7) x1 += segment-sum of H[et][src] per dst (CSR gather, no fp atomics)
    agg_kernel<<<N, DD>>>(N);

    // 8) y2 = relu(LN(x1)) with mlp affine
    {
        int blocks = (N + 7) / 8;
        ln_relu_kernel<<<blocks, blk>>>(x, node_type, mlp_gamma, mlp_beta, N, 1, 0);
    }

    // 9) out = x1 + y2 @ W_mlp[type] + b_mlp[type]  (type-bucketed)
    gemm128_kernel<2><<<dim3(gx, TTY), blk>>>(W_mlp, nullptr, b_mlp, out, N);
}

// round 3
// speedup vs baseline: 1.1227x; 1.1227x over previous
#include <cuda_runtime.h>
#include <cstdint>

// Problem constants (shapes fixed by setup_inputs)
#define NMAX 50000
#define EMAX 800000
#define DD   128
#define RR   8
#define TTY  4
#define SCHUNK 512

// ---------------- device scratch (no allocations allowed) ----------------
__device__ float g_y [(size_t)NMAX * DD];           // 25.6 MB  (y1, then y2)
__device__ float g_h [(size_t)RR * NMAX * DD];      // 204.8 MB (per-relation transformed feats)
__device__ float g_x1[(size_t)NMAX * DD];           // 25.6 MB  (x after conv residual)
__device__ int   g_deg[NMAX + 1];
__device__ int   g_off[NMAX + 1];
__device__ int   g_cur[NMAX];
__device__ int   g_ebuf[EMAX];                      // packed (edge_type<<16)|src
__device__ int   g_tcnt[TTY], g_toff[TTY], g_tcur[TTY];
__device__ int   g_perm[NMAX];                      // node ids grouped by type
__device__ int   g_bsum[256];                       // scan block partials

// ---------------- small kernels ----------------

__global__ void zero_kernel(int N) {
    int i = blockIdx.x * blockDim.x + threadIdx.x;
    if (i < N) g_deg[i] = 0;
    if (i < TTY) g_tcnt[i] = 0;
}

// LayerNorm (per-node-type affine) + ReLU. One warp per node.
__global__ void ln_relu_kernel(const float* __restrict__ xin,
                               const int*   __restrict__ ntype,
                               const float* __restrict__ gamma,
                               const float* __restrict__ beta,
                               int N, int use_internal, int count_types) {
    int gwarp = (blockIdx.x * blockDim.x + threadIdx.x) >> 5;
    int lane  = threadIdx.x & 31;
    if (gwarp >= N) return;
    const float* src = use_internal ? g_x1 : xin;
    const float4* xr = (const float4*)(src + (size_t)gwarp * DD);
    float4 v = xr[lane];
    float s  = v.x + v.y + v.z + v.w;
    float sq = v.x*v.x + v.y*v.y + v.z*v.z + v.w*v.w;
    #pragma unroll
    for (int d = 16; d; d >>= 1) {
        s  += __shfl_xor_sync(0xFFFFFFFFu, s,  d);
        sq += __shfl_xor_sync(0xFFFFFFFFu, sq, d);
    }
    float mu  = s * (1.0f / DD);
    float var = sq * (1.0f / DD) - mu * mu;
    float rs  = rsqrtf(var + 1e-5f);
    int t = ntype[gwarp];
    float4 g = ((const float4*)(gamma + (size_t)t * DD))[lane];
    float4 b = ((const float4*)(beta  + (size_t)t * DD))[lane];
    float4 o;
    o.x = fmaxf((v.x - mu) * rs * g.x + b.x, 0.0f);
    o.y = fmaxf((v.y - mu) * rs * g.y + b.y, 0.0f);
    o.z = fmaxf((v.z - mu) * rs * g.z + b.z, 0.0f);
    o.w = fmaxf((v.w - mu) * rs * g.w + b.w, 0.0f);
    ((float4*)(g_y + (size_t)gwarp * DD))[lane] = o;
    if (count_types && lane == 0) atomicAdd(&g_tcnt[t], 1);
}

__global__ void count_edges_kernel(const int* __restrict__ edst, int E) {
    int i = blockIdx.x * blockDim.x + threadIdx.x;
    if (i < E) atomicAdd(&g_deg[edst[i]], 1);
}

// ---- 3-phase parallel exclusive scan of g_deg -> g_off/g_cur ----

// Phase 1: per-block partial sums (512 elements per block, 256 threads)
__global__ void scan1_kernel(int N) {
    int b = blockIdx.x, t = threadIdx.x;
    int i = b * SCHUNK + t * 2;
    int s = 0;
    if (i < N)     s += g_deg[i];
    if (i + 1 < N) s += g_deg[i + 1];
    #pragma unroll
    for (int d = 16; d; d >>= 1) s += __shfl_xor_sync(0xFFFFFFFFu, s, d);
    __shared__ int red[8];
    if ((t & 31) == 0) red[t >> 5] = s;
    __syncthreads();
    if (t == 0) {
        int tot = 0;
        #pragma unroll
        for (int w = 0; w < 8; w++) tot += red[w];
        g_bsum[b] = tot;
    }
}

// Phase 2: exclusive scan of block partials (nb <= 256); type-bucket offsets; g_off[N]=E
__global__ void scan2_kernel(int nb, int N, int E) {
    int t = threadIdx.x;   // 256 threads
    int v = (t < nb) ? g_bsum[t] : 0;
    int x = v;
    #pragma unroll
    for (int d = 1; d < 32; d <<= 1) {
        int n = __shfl_up_sync(0xFFFFFFFFu, x, d);
        if ((t & 31) >= d) x += n;
    }
    __shared__ int ws[8];
    if ((t & 31) == 31) ws[t >> 5] = x;
    __syncthreads();
    if (t == 0) {
        int r = 0;
        #pragma unroll
        for (int w = 0; w < 8; w++) { int y = ws[w]; ws[w] = r; r += y; }
    }
    __syncthreads();
    int incl = x + ws[t >> 5];
    if (t < nb) g_bsum[t] = incl - v;   // exclusive
    if (t == 0) {
        g_off[N] = E;
        int r = 0;
        #pragma unroll
        for (int tt = 0; tt < TTY; tt++) {
            g_toff[tt] = r; g_tcur[tt] = r; r += g_tcnt[tt];
        }
    }
}

// Phase 3: per-block scan + write offsets
__global__ void scan3_kernel(int N) {
    int b = blockIdx.x, t = threadIdx.x;
    int i = b * SCHUNK + t * 2;
    int x0 = (i < N)     ? g_deg[i]     : 0;
    int x1 = (i + 1 < N) ? g_deg[i + 1] : 0;
    int s = x0 + x1;
    int x = s;
    #pragma unroll
    for (int d = 1; d < 32; d <<= 1) {
        int n = __shfl_up_sync(0xFFFFFFFFu, x, d);
        if ((t & 31) >= d) x += n;
    }
    __shared__ int ws[8];
    if ((t & 31) == 31) ws[t >> 5] = x;
    __syncthreads();
    if (t == 0) {
        int r = 0;
        #pragma unroll
        for (int w = 0; w < 8; w++) { int y = ws[w]; ws[w] = r; r += y; }
    }
    __syncthreads();
    int excl = (x + ws[t >> 5]) - s;
    int off = g_bsum[b] + excl;
    if (i < N)     { g_off[i]     = off;      g_cur[i]     = off; }
    if (i + 1 < N) { g_off[i + 1] = off + x0; g_cur[i + 1] = off + x0; }
}

__global__ void scatter_edges_kernel(const int* __restrict__ esrc,
                                     const int* __restrict__ edst,
                                     const int* __restrict__ etype, int E) {
    int i = blockIdx.x * blockDim.x + threadIdx.x;
    if (i < E) {
        int p = atomicAdd(&g_cur[edst[i]], 1);
        g_ebuf[p] = (etype[i] << 16) | esrc[i];
    }
}

__global__ void scatter_perm_kernel(const int* __restrict__ ntype, int N) {
    int i = blockIdx.x * blockDim.x + threadIdx.x;
    if (i < N) {
        int t = ntype[i];
        int p = atomicAdd(&g_tcur[t], 1);
        g_perm[p] = i;
    }
}

// Per-dst aggregation: x1[j] += sum over incident edges of H[et][src].
__global__ void agg_kernel(int N) {
    int j = blockIdx.x;
    int d = threadIdx.x;
    int beg = g_off[j], end = g_off[j + 1];
    float acc = g_x1[(size_t)j * DD + d];
    for (int k = beg; k < end; k++) {
        int p = g_ebuf[k];
        int src = p & 0xFFFF;
        int et  = p >> 16;
        acc += g_h[((size_t)et * N + src) * DD + d];
    }
    g_x1[(size_t)j * DD + d] = acc;
}

// ---------------- tf32 tensor-core GEMM (mma.sync m16n8k8) ----------------
// C[M,128] = A[M,128] @ B[128,128] (+ epilogue), 128x128 block tile, K-chunks of 32.
// MODE 0: H GEMM.  blockIdx.y = relation r.  A=g_y, B=Bp+r*D*D, C=g_h+r*M*D.
// MODE 1: root.    A=g_y, B=Bp, C=g_x1, C += ADDp (the original x).
// MODE 2: MLP.     blockIdx.y = type t. rows via g_perm bucket; C=Cp (d_out),
//                  += g_x1 row + bias.

__device__ __forceinline__ uint32_t f2tf32(float x) {
    uint32_t r;
    asm("cvt.rna.tf32.f32 %0, %1;" : "=r"(r) : "f"(x));
    return r;
}

__device__ __forceinline__ void mma_tf32(float& c0, float& c1, float& c2, float& c3,
                                         uint32_t a0, uint32_t a1, uint32_t a2, uint32_t a3,
                                         uint32_t b0, uint32_t b1) {
    asm volatile(
        "mma.sync.aligned.m16n8k8.row.col.f32.tf32.tf32.f32 "
        "{%0,%1,%2,%3}, {%4,%5,%6,%7}, {%8,%9}, {%0,%1,%2,%3};\n"
        : "+f"(c0), "+f"(c1), "+f"(c2), "+f"(c3)
        : "r"(a0), "r"(a1), "r"(a2), "r"(a3), "r"(b0), "r"(b1));
}

template<int MODE>
__global__ __launch_bounds__(256, 2)
void gemm_tc_kernel(const float* __restrict__ Bp,
                    const float* __restrict__ ADDp,
                    const float* __restrict__ biasp,
                    float* __restrict__ Cp,
                    int M) {
    // Padded strides: A frag LDS hits 32 distinct banks (pad 36),
    // B frag LDS hits 32 distinct banks (pad 136).
    __shared__ float As[128][36];
    __shared__ float Bs[32][136];

    const int tid = threadIdx.x;
    const int sel = blockIdx.y;

    const float* A = g_y;
    const float* B;
    float* C;
    const float* ADD = nullptr;
    const float* bias = nullptr;
    const int* perm = nullptr;
    int Mloc = M;

    if (MODE == 0) {
        B = Bp + (size_t)sel * DD * DD;
        C = g_h + (size_t)sel * M * DD;
    } else if (MODE == 1) {
        B = Bp;
        C = g_x1;
        ADD = ADDp;
    } else {
        B = Bp + (size_t)sel * DD * DD;
        bias = biasp + (size_t)sel * DD;
        C = Cp;
        ADD = g_x1;
        Mloc = g_tcnt[sel];
        perm = g_perm + g_toff[sel];
    }

    const int m0 = blockIdx.x * 128;
    if (m0 >= Mloc) return;

    // A loader: row = tid>>1 (0..127), 16 cols starting at (tid&1)*16
    const int lrow = tid >> 1;
    const int lcb  = (tid & 1) * 16;
    const int gr = m0 + lrow;
    const bool arow_valid = gr < Mloc;
    int arow = 0;
    if (arow_valid) arow = (MODE == 2) ? perm[gr] : gr;

    // B loader: row = tid>>3 (0..31), 16 cols starting at (tid&7)*16
    const int brow = tid >> 3;
    const int bcb  = (tid & 7) * 16;

    const int wid  = tid >> 5;
    const int wm   = wid & 3;      // warp grid 4 (M) x 2 (N)
    const int wn   = wid >> 2;
    const int lane = tid & 31;
    const int g    = lane >> 2;    // 0..7
    const int q    = lane & 3;     // 0..3

    float acc[2][8][4];
    #pragma unroll
    for (int mt = 0; mt < 2; mt++)
        #pragma unroll
        for (int nt = 0; nt < 8; nt++)
            #pragma unroll
            for (int r = 0; r < 4; r++) acc[mt][nt][r] = 0.0f;

    for (int kc = 0; kc < 4; kc++) {
        const int kb = kc * 32;

        // stage A chunk (convert to tf32)
        #pragma unroll
        for (int j = 0; j < 4; j++) {
            const int col = lcb + j * 4;
            float4 v = make_float4(0.f, 0.f, 0.f, 0.f);
            if (arow_valid) v = *(const float4*)&A[(size_t)arow * DD + kb + col];
            uint4 w;
            w.x = f2tf32(v.x); w.y = f2tf32(v.y);
            w.z = f2tf32(v.z); w.w = f2tf32(v.w);
            *(uint4*)&As[lrow][col] = w;
        }
        // stage B chunk
        #pragma unroll
        for (int j = 0; j < 4; j++) {
            const int col = bcb + j * 4;
            float4 v = *(const float4*)&B[(size_t)(kb + brow) * DD + col];
            uint4 w;
            w.x = f2tf32(v.x); w.y = f2tf32(v.y);
            w.z = f2tf32(v.z); w.w = f2tf32(v.w);
            *(uint4*)&Bs[brow][col] = w;
        }
        __syncthreads();

        #pragma unroll
        for (int ks = 0; ks < 4; ks++) {
            const int k0 = ks * 8;
            uint32_t af[2][4];
            #pragma unroll
            for (int mt = 0; mt < 2; mt++) {
                const int r0 = wm * 32 + mt * 16 + g;
                af[mt][0] = __float_as_uint(As[r0    ][k0 + q]);
                af[mt][1] = __float_as_uint(As[r0 + 8][k0 + q]);
                af[mt][2] = __float_as_uint(As[r0    ][k0 + q + 4]);
                af[mt][3] = __float_as_uint(As[r0 + 8][k0 + q + 4]);
            }
            uint32_t bf[8][2];
            #pragma unroll
            for (int nt = 0; nt < 8; nt++) {
                const int cn = wn * 64 + nt * 8 + g;
                bf[nt][0] = __float_as_uint(Bs[k0 + q    ][cn]);
                bf[nt][1] = __float_as_uint(Bs[k0 + q + 4][cn]);
            }
            #pragma unroll
            for (int mt = 0; mt < 2; mt++)
                #pragma unroll
                for (int nt = 0; nt < 8; nt++)
                    mma_tf32(acc[mt][nt][0], acc[mt][nt][1], acc[mt][nt][2], acc[mt][nt][3],
                             af[mt][0], af[mt][1], af[mt][2], af[mt][3],
                             bf[nt][0], bf[nt][1]);
        }
        __syncthreads();
    }

    // epilogue
    #pragma unroll
    for (int mt = 0; mt < 2; mt++) {
        #pragma unroll
        for (int half = 0; half < 2; half++) {
            const int rl  = wm * 32 + mt * 16 + half * 8 + g;
            const int grr = m0 + rl;
            if (grr >= Mloc) continue;
            const int prow = (MODE == 2) ? perm[grr] : grr;
            const size_t base = (size_t)prow * DD;
            #pragma unroll
            for (int nt = 0; nt < 8; nt++) {
                const int col = wn * 64 + nt * 8 + q * 2;
                float2 o;
                o.x = acc[mt][nt][half * 2 + 0];
                o.y = acc[mt][nt][half * 2 + 1];
                if (MODE >= 1) {
                    float2 ad = *(const float2*)&ADD[base + col];
                    o.x += ad.x; o.y += ad.y;
                }
                if (MODE == 2) {
                    float2 bb = *(const float2*)&bias[col];
                    o.x += bb.x; o.y += bb.y;
                }
                *(float2*)&C[base + col] = o;
            }
        }
    }
}

// ---------------- host launcher ----------------
extern "C" void kernel_launch(void* const* d_in, const int* in_sizes, int n_in,
                              void* d_out, int out_size) {
    const float* x          = (const float*)d_in[0];
    const int*   edge_src   = (const int*)  d_in[1];
    const int*   edge_dst   = (const int*)  d_in[2];
    const int*   node_type  = (const int*)  d_in[3];
    const int*   edge_type  = (const int*)  d_in[4];
    const float* conv_gamma = (const float*)d_in[5];
    const float* conv_beta  = (const float*)d_in[6];
    const float* W_rel      = (const float*)d_in[7];
    const float* W_root     = (const float*)d_in[8];
    const float* mlp_gamma  = (const float*)d_in[9];
    const float* mlp_beta   = (const float*)d_in[10];
    const float* W_mlp      = (const float*)d_in[11];
    const float* b_mlp      = (const float*)d_in[12];
    float* out = (float*)d_out;

    const int N = in_sizes[0] / DD;
    const int E = in_sizes[1];

    const int THR = 256;
    dim3 blk(THR);
    const int nb = (N + SCHUNK - 1) / SCHUNK;

    // 0) zero counters
    zero_kernel<<<(N + THR - 1) / THR, blk>>>(N);

    // 1) y1 = relu(LN(x)) with conv affine; also count node types
    ln_relu_kernel<<<(N + 7) / 8, blk>>>(x, node_type, conv_gamma, conv_beta, N, 0, 1);

    // 2) CSR build: degree histogram
    count_edges_kernel<<<(E + THR - 1) / THR, blk>>>(edge_dst, E);

    // 3) parallel scan -> offsets (also type offsets)
    scan1_kernel<<<nb, blk>>>(N);
    scan2_kernel<<<1, blk>>>(nb, N, E);
    scan3_kernel<<<nb, blk>>>(N);

    // 4) scatter edges into CSR; scatter node ids into type buckets
    scatter_edges_kernel<<<(E + THR - 1) / THR, blk>>>(edge_src, edge_dst, edge_type, E);
    scatter_perm_kernel<<<(N + THR - 1) / THR, blk>>>(node_type, N);

    const int gx = (N + 127) / 128;

    // 5) H_r = y1 @ W_rel[r]  (8 GEMMs, tensor cores)
    gemm_tc_kernel<0><<<dim3(gx, RR), blk>>>(W_rel, nullptr, nullptr, nullptr, N);

    // 6) x1 = x + y1 @ W_root
    gemm_tc_kernel<1><<<dim3(gx, 1), blk>>>(W_root, x, nullptr, nullptr, N);

    // 7) x1 += segment-sum of H[et][src] per dst (CSR gather, no fp atomics)
    agg_kernel<<<N, DD>>>(N);

    // 8) y2 = relu(LN(x1)) with mlp affine
    ln_relu_kernel<<<(N + 7) / 8, blk>>>(x, node_type, mlp_gamma, mlp_beta, N, 1, 0);

    // 9) out = x1 + y2 @ W_mlp[type] + b_mlp[type]  (type-bucketed, tensor cores)
    gemm_tc_kernel<2><<<dim3(gx, TTY), blk>>>(W_mlp, nullptr, b_mlp, out, N);
}

// round 6
// speedup vs baseline: 1.3637x; 1.2146x over previous
#include <cuda_runtime.h>
#include <cstdint>

// Problem constants (shapes fixed by setup_inputs)
#define NMAX 50000
#define EMAX 800000
#define DD   128
#define RR   8
#define TTY  4
#define N2MAX (RR * NMAX)
#define SCH   2048

// ---------------- device scratch (no allocations allowed) ----------------
__device__ float g_y [(size_t)NMAX * DD];           // y1, then y2
__device__ float g_x1[(size_t)NMAX * DD];           // x after conv residual
__device__ int   g_deg2[N2MAX + 1];                 // histogram over key=(r*N+dst)
__device__ int   g_off2[N2MAX + 1];
__device__ int   g_cur2[N2MAX];
__device__ int   g_esrc[EMAX];                      // src ids sorted by (r,dst)
__device__ int   g_tcnt[TTY], g_toff[TTY], g_tcur[TTY];
__device__ int   g_perm[NMAX];                      // node ids grouped by type
__device__ int   g_bsum[256];                       // scan block partials

// ---------------- small kernels ----------------

__global__ void zero_kernel(int N2) {
    int i = blockIdx.x * blockDim.x + threadIdx.x;
    if (i < N2) g_deg2[i] = 0;
    if (i < TTY) g_tcnt[i] = 0;
}

// LayerNorm (per-node-type affine) + ReLU. One warp per node.
__global__ void ln_relu_kernel(const float* __restrict__ xin,
                               const int*   __restrict__ ntype,
                               const float* __restrict__ gamma,
                               const float* __restrict__ beta,
                               int N, int use_internal, int count_types) {
    int gwarp = (blockIdx.x * blockDim.x + threadIdx.x) >> 5;
    int lane  = threadIdx.x & 31;
    if (gwarp >= N) return;
    const float* src = use_internal ? g_x1 : xin;
    float4 v = ((const float4*)(src + (size_t)gwarp * DD))[lane];
    float s  = v.x + v.y + v.z + v.w;
    float sq = v.x*v.x + v.y*v.y + v.z*v.z + v.w*v.w;
    #pragma unroll
    for (int d = 16; d; d >>= 1) {
        s  += __shfl_xor_sync(0xFFFFFFFFu, s,  d);
        sq += __shfl_xor_sync(0xFFFFFFFFu, sq, d);
    }
    float mu  = s * (1.0f / DD);
    float var = sq * (1.0f / DD) - mu * mu;
    float rs  = rsqrtf(var + 1e-5f);
    int t = ntype[gwarp];
    float4 g = ((const float4*)(gamma + (size_t)t * DD))[lane];
    float4 b = ((const float4*)(beta  + (size_t)t * DD))[lane];
    float4 o;
    o.x = fmaxf((v.x - mu) * rs * g.x + b.x, 0.0f);
    o.y = fmaxf((v.y - mu) * rs * g.y + b.y, 0.0f);
    o.z = fmaxf((v.z - mu) * rs * g.z + b.z, 0.0f);
    o.w = fmaxf((v.w - mu) * rs * g.w + b.w, 0.0f);
    ((float4*)(g_y + (size_t)gwarp * DD))[lane] = o;
    if (count_types && lane == 0) atomicAdd(&g_tcnt[t], 1);
}

__global__ void count_kernel(const int* __restrict__ edst,
                             const int* __restrict__ etype, int E, int N) {
    int i = blockIdx.x * blockDim.x + threadIdx.x;
    if (i < E) atomicAdd(&g_deg2[etype[i] * N + edst[i]], 1);
}

// ---- 3-phase parallel exclusive scan over N2 = R*N bins ----
__global__ void scan1_kernel(int NT) {
    int b = blockIdx.x, t = threadIdx.x;
    int base = b * SCH + t * 8;
    int s = 0;
    #pragma unroll
    for (int i = 0; i < 8; i++) { int idx = base + i; if (idx < NT) s += g_deg2[idx]; }
    #pragma unroll
    for (int d = 16; d; d >>= 1) s += __shfl_xor_sync(0xFFFFFFFFu, s, d);
    __shared__ int red[8];
    if ((t & 31) == 0) red[t >> 5] = s;
    __syncthreads();
    if (t == 0) {
        int tot = 0;
        #pragma unroll
        for (int w = 0; w < 8; w++) tot += red[w];
        g_bsum[b] = tot;
    }
}

__global__ void scan2_kernel(int nb, int NT, int E) {
    int t = threadIdx.x;
    int v = (t < nb) ? g_bsum[t] : 0;
    int x = v;
    #pragma unroll
    for (int d = 1; d < 32; d <<= 1) {
        int n = __shfl_up_sync(0xFFFFFFFFu, x, d);
        if ((t & 31) >= d) x += n;
    }
    __shared__ int ws[8];
    if ((t & 31) == 31) ws[t >> 5] = x;
    __syncthreads();
    if (t == 0) {
        int r = 0;
        #pragma unroll
        for (int w = 0; w < 8; w++) { int y = ws[w]; ws[w] = r; r += y; }
    }
    __syncthreads();
    int incl = x + ws[t >> 5];
    if (t < nb) g_bsum[t] = incl - v;
    if (t == 0) {
        g_off2[NT] = E;
        int r = 0;
        #pragma unroll
        for (int tt = 0; tt < TTY; tt++) {
            g_toff[tt] = r; g_tcur[tt] = r; r += g_tcnt[tt];
        }
    }
}

__global__ void scan3_kernel(int NT) {
    int b = blockIdx.x, t = threadIdx.x;
    int base = b * SCH + t * 8;
    int v[8]; int s = 0;
    #pragma unroll
    for (int i = 0; i < 8; i++) {
        int idx = base + i;
        v[i] = (idx < NT) ? g_deg2[idx] : 0;
        s += v[i];
    }
    int x = s;
    #pragma unroll
    for (int d = 1; d < 32; d <<= 1) {
        int n = __shfl_up_sync(0xFFFFFFFFu, x, d);
        if ((t & 31) >= d) x += n;
    }
    __shared__ int ws[8];
    if ((t & 31) == 31) ws[t >> 5] = x;
    __syncthreads();
    if (t == 0) {
        int r = 0;
        #pragma unroll
        for (int w = 0; w < 8; w++) { int y = ws[w]; ws[w] = r; r += y; }
    }
    __syncthreads();
    int run = g_bsum[b] + (x + ws[t >> 5]) - s;
    #pragma unroll
    for (int i = 0; i < 8; i++) {
        int idx = base + i;
        if (idx < NT) { g_off2[idx] = run; g_cur2[idx] = run; run += v[i]; }
    }
}

__global__ void scatter_edges_kernel(const int* __restrict__ esrc,
                                     const int* __restrict__ edst,
                                     const int* __restrict__ etype, int E, int N) {
    int i = blockIdx.x * blockDim.x + threadIdx.x;
    if (i < E) {
        int key = etype[i] * N + edst[i];
        int p = atomicAdd(&g_cur2[key], 1);
        g_esrc[p] = esrc[i];
    }
}

__global__ void scatter_perm_kernel(const int* __restrict__ ntype, int N) {
    int i = blockIdx.x * blockDim.x + threadIdx.x;
    if (i < N) {
        int p = atomicAdd(&g_tcur[ntype[i]], 1);
        g_perm[p] = i;
    }
}

// ---------------- tf32 mma.sync helpers ----------------
__device__ __forceinline__ uint32_t f2tf32(float x) {
    uint32_t r;
    asm("cvt.rna.tf32.f32 %0, %1;" : "=r"(r) : "f"(x));
    return r;
}

__device__ __forceinline__ void mma_tf32(float& c0, float& c1, float& c2, float& c3,
                                         uint32_t a0, uint32_t a1, uint32_t a2, uint32_t a3,
                                         uint32_t b0, uint32_t b1) {
    asm volatile(
        "mma.sync.aligned.m16n8k8.row.col.f32.tf32.tf32.f32 "
        "{%0,%1,%2,%3}, {%4,%5,%6,%7}, {%8,%9}, {%0,%1,%2,%3};\n"
        : "+f"(c0), "+f"(c1), "+f"(c2), "+f"(c3)
        : "r"(a0), "r"(a1), "r"(a2), "r"(a3), "r"(b0), "r"(b1));
}

// ---------------- fused conv GEMM (mma.sync tf32) ----------------
// CTA owns 128 dst rows. Loops r = 0..8 (8 relations + root):
//   A_r[row] = sum over edges (r,dst=row) of y1[src]   (root: A = y1[row])
//   acc += A_r @ W_r^T   accumulated in registers across all 9 passes.
// Epilogue: x1[row] = x[row] + acc[row].
// SMEM: As full tile 128x132 (tf32 bits), Bs chunk 32x136. 85KB dynamic.
#define AS_STRIDE 132
#define BS_STRIDE 136
#define CONV_SMEM ((128 * AS_STRIDE + 32 * BS_STRIDE) * 4)

__global__ __launch_bounds__(256, 2)
void conv_gemm_kernel(const float* __restrict__ x,
                      const float* __restrict__ W_rel,
                      const float* __restrict__ W_root,
                      int N) {
    extern __shared__ float smem[];
    float (*As)[AS_STRIDE] = (float (*)[AS_STRIDE])smem;
    float (*Bs)[BS_STRIDE] = (float (*)[BS_STRIDE])(smem + 128 * AS_STRIDE);

    const int tid  = threadIdx.x;
    const int wid  = tid >> 5;
    const int wm   = wid & 3;      // warp grid 4 (M) x 2 (N)
    const int wn   = wid >> 2;
    const int lane = tid & 31;
    const int g    = lane >> 2;    // 0..7
    const int q    = lane & 3;     // 0..3
    const int m0   = blockIdx.x * 128;

    // B loader mapping: row = tid>>3 (0..31), 16 cols at (tid&7)*16
    const int brow = tid >> 3;
    const int bcb  = (tid & 7) * 16;
    // A gather mapping: row = pass*64 + tid>>2, 32 cols at (tid&3)*32
    const int grow = tid >> 2;
    const int part = tid & 3;

    float acc[2][8][4];
    #pragma unroll
    for (int mt = 0; mt < 2; mt++)
        #pragma unroll
        for (int nt = 0; nt < 8; nt++)
            #pragma unroll
            for (int rr = 0; rr < 4; rr++) acc[mt][nt][rr] = 0.0f;

    for (int r = 0; r < 9; r++) {
        // ---- stage A: gathered + summed rows of y1 (full 128x128 tile) ----
        #pragma unroll 1
        for (int pass = 0; pass < 2; pass++) {
            const int row = pass * 64 + grow;
            const int m = m0 + row;
            float4 a[8];
            #pragma unroll
            for (int j = 0; j < 8; j++) a[j] = make_float4(0.f, 0.f, 0.f, 0.f);
            if (m < N) {
                if (r < 8) {
                    const int key = r * N + m;
                    const int beg = g_off2[key], end = g_off2[key + 1];
                    for (int p = beg; p < end; p++) {
                        const int s = g_esrc[p];
                        const float4* yr = (const float4*)(g_y + (size_t)s * DD) + part * 8;
                        #pragma unroll
                        for (int j = 0; j < 8; j++) {
                            float4 v = yr[j];
                            a[j].x += v.x; a[j].y += v.y;
                            a[j].z += v.z; a[j].w += v.w;
                        }
                    }
                } else {
                    const float4* yr = (const float4*)(g_y + (size_t)m * DD) + part * 8;
                    #pragma unroll
                    for (int j = 0; j < 8; j++) a[j] = yr[j];
                }
            }
            #pragma unroll
            for (int j = 0; j < 8; j++) {
                uint4 w;
                w.x = f2tf32(a[j].x); w.y = f2tf32(a[j].y);
                w.z = f2tf32(a[j].z); w.w = f2tf32(a[j].w);
                *(uint4*)&As[row][part * 32 + j * 4] = w;
            }
        }

        const float* W = (r < 8) ? (W_rel + (size_t)r * DD * DD) : W_root;

        #pragma unroll 1
        for (int kc = 0; kc < 4; kc++) {
            const int kb = kc * 32;
            // ---- stage B chunk: Bs[n? no: Bs[krow][ncol]] = W[kb+krow][ncol] ----
            #pragma unroll
            for (int j = 0; j < 4; j++) {
                const int col = bcb + j * 4;
                float4 v = *(const float4*)&W[(size_t)(kb + brow) * DD + col];
                uint4 w;
                w.x = f2tf32(v.x); w.y = f2tf32(v.y);
                w.z = f2tf32(v.z); w.w = f2tf32(v.w);
                *(uint4*)&Bs[brow][col] = w;
            }
            __syncthreads();

            #pragma unroll
            for (int ks = 0; ks < 4; ks++) {
                const int k0 = kb + ks * 8;
                const int kq = ks * 8;
                uint32_t af[2][4];
                #pragma unroll
                for (int mt = 0; mt < 2; mt++) {
                    const int r0 = wm * 32 + mt * 16 + g;
                    af[mt][0] = __float_as_uint(As[r0    ][k0 + q]);
                    af[mt][1] = __float_as_uint(As[r0 + 8][k0 + q]);
                    af[mt][2] = __float_as_uint(As[r0    ][k0 + q + 4]);
                    af[mt][3] = __float_as_uint(As[r0 + 8][k0 + q + 4]);
                }
                uint32_t bf[8][2];
                #pragma unroll
                for (int nt = 0; nt < 8; nt++) {
                    const int cn = wn * 64 + nt * 8 + g;
                    bf[nt][0] = __float_as_uint(Bs[kq + q    ][cn]);
                    bf[nt][1] = __float_as_uint(Bs[kq + q + 4][cn]);
                }
                #pragma unroll
                for (int mt = 0; mt < 2; mt++)
                    #pragma unroll
                    for (int nt = 0; nt < 8; nt++)
                        mma_tf32(acc[mt][nt][0], acc[mt][nt][1], acc[mt][nt][2], acc[mt][nt][3],
                                 af[mt][0], af[mt][1], af[mt][2], af[mt][3],
                                 bf[nt][0], bf[nt][1]);
            }
            __syncthreads();
        }
    }

    // epilogue: x1 = x + acc
    #pragma unroll
    for (int mt = 0; mt < 2; mt++) {
        #pragma unroll
        for (int half = 0; half < 2; half++) {
            const int rl = wm * 32 + mt * 16 + half * 8 + g;
            const int m  = m0 + rl;
            if (m >= N) continue;
            const size_t base = (size_t)m * DD;
            #pragma unroll
            for (int nt = 0; nt < 8; nt++) {
                const int col = wn * 64 + nt * 8 + q * 2;
                float2 ad = *(const float2*)&x[base + col];
                float2 o;
                o.x = acc[mt][nt][half * 2 + 0] + ad.x;
                o.y = acc[mt][nt][half * 2 + 1] + ad.y;
                *(float2*)&g_x1[base + col] = o;
            }
        }
    }
}

// ---------------- MLP GEMM (mma.sync tf32, type-bucketed) ----------------
// out[perm_row] = x1[perm_row] + b_mlp[t] + y2[perm_row] @ W_mlp[t]
__global__ __launch_bounds__(256, 2)
void mlp_gemm_kernel(const float* __restrict__ W_mlp,
                     const float* __restrict__ biasp,
                     float* __restrict__ out,
                     int N) {
    __shared__ float As[128][36];
    __shared__ float Bs[32][136];

    const int tid = threadIdx.x;
    const int ty  = blockIdx.y;
    const int Mloc = g_tcnt[ty];
    const int m0 = blockIdx.x * 128;
    if (m0 >= Mloc) return;
    const int* perm = g_perm + g_toff[ty];
    const float* B = W_mlp + (size_t)ty * DD * DD;
    const float* bias = biasp + (size_t)ty * DD;

    const int lrow = tid >> 1;
    const int lcb  = (tid & 1) * 16;
    const int gr = m0 + lrow;
    const bool arow_valid = gr < Mloc;
    int arow = 0;
    if (arow_valid) arow = perm[gr];

    const int brow = tid >> 3;
    const int bcb  = (tid & 7) * 16;

    const int wid  = tid >> 5;
    const int wm   = wid & 3;
    const int wn   = wid >> 2;
    const int lane = tid & 31;
    const int g    = lane >> 2;
    const int q    = lane & 3;

    float acc[2][8][4];
    #pragma unroll
    for (int mt = 0; mt < 2; mt++)
        #pragma unroll
        for (int nt = 0; nt < 8; nt++)
            #pragma unroll
            for (int rr = 0; rr < 4; rr++) acc[mt][nt][rr] = 0.0f;

    for (int kc = 0; kc < 4; kc++) {
        const int kb = kc * 32;
        #pragma unroll
        for (int j = 0; j < 4; j++) {
            const int col = lcb + j * 4;
            float4 v = make_float4(0.f, 0.f, 0.f, 0.f);
            if (arow_valid) v = *(const float4*)&g_y[(size_t)arow * DD + kb + col];
            uint4 w;
            w.x = f2tf32(v.x); w.y = f2tf32(v.y);
            w.z = f2tf32(v.z); w.w = f2tf32(v.w);
            *(uint4*)&As[lrow][col] = w;
        }
        #pragma unroll
        for (int j = 0; j < 4; j++) {
            const int col = bcb + j * 4;
            float4 v = *(const float4*)&B[(size_t)(kb + brow) * DD + col];
            uint4 w;
            w.x = f2tf32(v.x); w.y = f2tf32(v.y);
            w.z = f2tf32(v.z); w.w = f2tf32(v.w);
            *(uint4*)&Bs[brow][col] = w;
        }
        __syncthreads();

        #pragma unroll
        for (int ks = 0; ks < 4; ks++) {
            const int k0 = ks * 8;
            uint32_t af[2][4];
            #pragma unroll
            for (int mt = 0; mt < 2; mt++) {
                const int r0 = wm * 32 + mt * 16 + g;
                af[mt][0] = __float_as_uint(As[r0    ][k0 + q]);
                af[mt][1] = __float_as_uint(As[r0 + 8][k0 + q]);
                af[mt][2] = __float_as_uint(As[r0    ][k0 + q + 4]);
                af[mt][3] = __float_as_uint(As[r0 + 8][k0 + q + 4]);
            }
            uint32_t bf[8][2];
            #pragma unroll
            for (int nt = 0; nt < 8; nt++) {
                const int cn = wn * 64 + nt * 8 + g;
                bf[nt][0] = __float_as_uint(Bs[k0 + q    ][cn]);
                bf[nt][1] = __float_as_uint(Bs[k0 + q + 4][cn]);
            }
            #pragma unroll
            for (int mt = 0; mt < 2; mt++)
                #pragma unroll
                for (int nt = 0; nt < 8; nt++)
                    mma_tf32(acc[mt][nt][0], acc[mt][nt][1], acc[mt][nt][2], acc[mt][nt][3],
                             af[mt][0], af[mt][1], af[mt][2], af[mt][3],
                             bf[nt][0], bf[nt][1]);
        }
        __syncthreads();
    }

    #pragma unroll
    for (int mt = 0; mt < 2; mt++) {
        #pragma unroll
        for (int half = 0; half < 2; half++) {
            const int rl  = wm * 32 + mt * 16 + half * 8 + g;
            const int grr = m0 + rl;
            if (grr >= Mloc) continue;
            const int prow = perm[grr];
            const size_t base = (size_t)prow * DD;
            #pragma unroll
            for (int nt = 0; nt < 8; nt++) {
                const int col = wn * 64 + nt * 8 + q * 2;
                float2 ad = *(const float2*)&g_x1[base + col];
                float2 bb = *(const float2*)&bias[col];
                float2 o;
                o.x = acc[mt][nt][half * 2 + 0] + ad.x + bb.x;
                o.y = acc[mt][nt][half * 2 + 1] + ad.y + bb.y;
                *(float2*)&out[base + col] = o;
            }
        }
    }
}

// ---------------- host launcher ----------------
extern "C" void kernel_launch(void* const* d_in, const int* in_sizes, int n_in,
                              void* d_out, int out_size) {
    const float* x          = (const float*)d_in[0];
    const int*   edge_src   = (const int*)  d_in[1];
    const int*   edge_dst   = (const int*)  d_in[2];
    const int*   node_type  = (const int*)  d_in[3];
    const int*   edge_type  = (const int*)  d_in[4];
    const float* conv_gamma = (const float*)d_in[5];
    const float* conv_beta  = (const float*)d_in[6];
    const float* W_rel      = (const float*)d_in[7];
    const float* W_root     = (const float*)d_in[8];
    const float* mlp_gamma  = (const float*)d_in[9];
    const float* mlp_beta   = (const float*)d_in[10];
    const float* W_mlp      = (const float*)d_in[11];
    const float* b_mlp      = (const float*)d_in[12];
    float* out = (float*)d_out;

    const int N  = in_sizes[0] / DD;
    const int E  = in_sizes[1];
    const int N2 = RR * N;

    static int attr_done = 0;
    if (!attr_done) {
        cudaFuncSetAttribute(conv_gemm_kernel,
                             cudaFuncAttributeMaxDynamicSharedMemorySize, CONV_SMEM);
        attr_done = 1;
    }

    const int THR = 256;
    dim3 blk(THR);
    const int nb = (N2 + SCH - 1) / SCH;
    const int gx = (N + 127) / 128;

    zero_kernel<<<(N2 + THR - 1) / THR, blk>>>(N2);
    ln_relu_kernel<<<(N + 7) / 8, blk>>>(x, node_type, conv_gamma, conv_beta, N, 0, 1);
    count_kernel<<<(E + THR - 1) / THR, blk>>>(edge_dst, edge_type, E, N);
    scan1_kernel<<<nb, blk>>>(N2);
    scan2_kernel<<<1, blk>>>(nb, N2, E);
    scan3_kernel<<<nb, blk>>>(N2);
    scatter_edges_kernel<<<(E + THR - 1) / THR, blk>>>(edge_src, edge_dst, edge_type, E, N);
    scatter_perm_kernel<<<(N + THR - 1) / THR, blk>>>(node_type, N);

    // fused conv: x1 = x + sum_r Z_r @ W_r + y1 @ W_root  (gather + mma.sync tf32)
    conv_gemm_kernel<<<gx, blk, CONV_SMEM>>>(x, W_rel, W_root, N);

    ln_relu_kernel<<<(N + 7) / 8, blk>>>(x, node_type, mlp_gamma, mlp_beta, N, 1, 0);

    // MLP: out = x1 + y2 @ W_mlp[type] + b_mlp[type]  (type-bucketed)
    mlp_gemm_kernel<<<dim3(gx, TTY), blk>>>(W_mlp, b_mlp, out, N);
}

// round 7
// speedup vs baseline: 1.9708x; 1.4452x over previous
#include <cuda_runtime.h>
#include <cuda_fp16.h>
#include <cstdint>

// Problem constants (shapes fixed by setup_inputs)
#define NMAX 50000
#define EMAX 800000
#define DD   128
#define RR   8
#define TTY  4
#define N2MAX (RR * NMAX)
#define SCH   2048

// ---------------- device scratch (no allocations allowed) ----------------
__device__ __half g_yh[(size_t)NMAX * DD];          // y1 then y2, fp16 (12.8MB, L2-resident)
__device__ float  g_x1[(size_t)NMAX * DD];          // x after conv residual
__device__ int    g_deg2[N2MAX + 1];                // histogram over key=(r*N+dst)
__device__ int    g_off2[N2MAX + 1];
__device__ int    g_cur2[N2MAX];
__device__ int    g_esrc[EMAX];                     // src ids sorted by (r,dst)
__device__ int    g_tcnt[TTY], g_toff[TTY], g_tcur[TTY];
__device__ int    g_perm[NMAX];                     // node ids grouped by type
__device__ int    g_bsum[256];                      // scan block partials

// ---------------- helpers ----------------
__device__ __forceinline__ uint32_t pack2(float a, float b) {
    __half2 h = __floats2half2_rn(a, b);
    return *(uint32_t*)&h;
}
__device__ __forceinline__ float2 unp2(uint32_t w) {
    __half2 h = *(__half2*)&w;
    return __half22float2(h);
}

__device__ __forceinline__ void mma_f16(float& c0, float& c1, float& c2, float& c3,
                                        uint32_t a0, uint32_t a1, uint32_t a2, uint32_t a3,
                                        uint32_t b0, uint32_t b1) {
    asm volatile(
        "mma.sync.aligned.m16n8k16.row.col.f32.f16.f16.f32 "
        "{%0,%1,%2,%3}, {%4,%5,%6,%7}, {%8,%9}, {%0,%1,%2,%3};\n"
        : "+f"(c0), "+f"(c1), "+f"(c2), "+f"(c3)
        : "r"(a0), "r"(a1), "r"(a2), "r"(a3), "r"(b0), "r"(b1));
}

// ---------------- small kernels ----------------

__global__ void zero_kernel(int N2) {
    int i = blockIdx.x * blockDim.x + threadIdx.x;
    if (i < N2) g_deg2[i] = 0;
    if (i < TTY) g_tcnt[i] = 0;
}

// LayerNorm (per-node-type affine) + ReLU -> fp16. One warp per node.
__global__ void ln_relu_kernel(const float* __restrict__ xin,
                               const int*   __restrict__ ntype,
                               const float* __restrict__ gamma,
                               const float* __restrict__ beta,
                               int N, int use_internal, int count_types) {
    int gwarp = (blockIdx.x * blockDim.x + threadIdx.x) >> 5;
    int lane  = threadIdx.x & 31;
    if (gwarp >= N) return;
    const float* src = use_internal ? g_x1 : xin;
    float4 v = ((const float4*)(src + (size_t)gwarp * DD))[lane];
    float s  = v.x + v.y + v.z + v.w;
    float sq = v.x*v.x + v.y*v.y + v.z*v.z + v.w*v.w;
    #pragma unroll
    for (int d = 16; d; d >>= 1) {
        s  += __shfl_xor_sync(0xFFFFFFFFu, s,  d);
        sq += __shfl_xor_sync(0xFFFFFFFFu, sq, d);
    }
    float mu  = s * (1.0f / DD);
    float var = sq * (1.0f / DD) - mu * mu;
    float rs  = rsqrtf(var + 1e-5f);
    int t = ntype[gwarp];
    float4 g = ((const float4*)(gamma + (size_t)t * DD))[lane];
    float4 b = ((const float4*)(beta  + (size_t)t * DD))[lane];
    float o0 = fmaxf((v.x - mu) * rs * g.x + b.x, 0.0f);
    float o1 = fmaxf((v.y - mu) * rs * g.y + b.y, 0.0f);
    float o2 = fmaxf((v.z - mu) * rs * g.z + b.z, 0.0f);
    float o3 = fmaxf((v.w - mu) * rs * g.w + b.w, 0.0f);
    uint2 pw;
    pw.x = pack2(o0, o1);
    pw.y = pack2(o2, o3);
    ((uint2*)(g_yh + (size_t)gwarp * DD))[lane] = pw;
    if (count_types && lane == 0) atomicAdd(&g_tcnt[t], 1);
}

__global__ void count_kernel(const int* __restrict__ edst,
                             const int* __restrict__ etype, int E, int N) {
    int i = blockIdx.x * blockDim.x + threadIdx.x;
    if (i < E) atomicAdd(&g_deg2[etype[i] * N + edst[i]], 1);
}

// ---- 3-phase parallel exclusive scan over N2 = R*N bins ----
__global__ void scan1_kernel(int NT) {
    int b = blockIdx.x, t = threadIdx.x;
    int base = b * SCH + t * 8;
    int s = 0;
    #pragma unroll
    for (int i = 0; i < 8; i++) { int idx = base + i; if (idx < NT) s += g_deg2[idx]; }
    #pragma unroll
    for (int d = 16; d; d >>= 1) s += __shfl_xor_sync(0xFFFFFFFFu, s, d);
    __shared__ int red[8];
    if ((t & 31) == 0) red[t >> 5] = s;
    __syncthreads();
    if (t == 0) {
        int tot = 0;
        #pragma unroll
        for (int w = 0; w < 8; w++) tot += red[w];
        g_bsum[b] = tot;
    }
}

__global__ void scan2_kernel(int nb, int NT, int E) {
    int t = threadIdx.x;
    int v = (t < nb) ? g_bsum[t] : 0;
    int x = v;
    #pragma unroll
    for (int d = 1; d < 32; d <<= 1) {
        int n = __shfl_up_sync(0xFFFFFFFFu, x, d);
        if ((t & 31) >= d) x += n;
    }
    __shared__ int ws[8];
    if ((t & 31) == 31) ws[t >> 5] = x;
    __syncthreads();
    if (t == 0) {
        int r = 0;
        #pragma unroll
        for (int w = 0; w < 8; w++) { int y = ws[w]; ws[w] = r; r += y; }
    }
    __syncthreads();
    int incl = x + ws[t >> 5];
    if (t < nb) g_bsum[t] = incl - v;
    if (t == 0) {
        g_off2[NT] = E;
        int r = 0;
        #pragma unroll
        for (int tt = 0; tt < TTY; tt++) {
            g_toff[tt] = r; g_tcur[tt] = r; r += g_tcnt[tt];
        }
    }
}

__global__ void scan3_kernel(int NT) {
    int b = blockIdx.x, t = threadIdx.x;
    int base = b * SCH + t * 8;
    int v[8]; int s = 0;
    #pragma unroll
    for (int i = 0; i < 8; i++) {
        int idx = base + i;
        v[i] = (idx < NT) ? g_deg2[idx] : 0;
        s += v[i];
    }
    int x = s;
    #pragma unroll
    for (int d = 1; d < 32; d <<= 1) {
        int n = __shfl_up_sync(0xFFFFFFFFu, x, d);
        if ((t & 31) >= d) x += n;
    }
    __shared__ int ws[8];
    if ((t & 31) == 31) ws[t >> 5] = x;
    __syncthreads();
    if (t == 0) {
        int r = 0;
        #pragma unroll
        for (int w = 0; w < 8; w++) { int y = ws[w]; ws[w] = r; r += y; }
    }
    __syncthreads();
    int run = g_bsum[b] + (x + ws[t >> 5]) - s;
    #pragma unroll
    for (int i = 0; i < 8; i++) {
        int idx = base + i;
        if (idx < NT) { g_off2[idx] = run; g_cur2[idx] = run; run += v[i]; }
    }
}

__global__ void scatter_edges_kernel(const int* __restrict__ esrc,
                                     const int* __restrict__ edst,
                                     const int* __restrict__ etype, int E, int N) {
    int i = blockIdx.x * blockDim.x + threadIdx.x;
    if (i < E) {
        int key = etype[i] * N + edst[i];
        int p = atomicAdd(&g_cur2[key], 1);
        g_esrc[p] = esrc[i];
    }
}

__global__ void scatter_perm_kernel(const int* __restrict__ ntype, int N) {
    int i = blockIdx.x * blockDim.x + threadIdx.x;
    if (i < N) {
        int p = atomicAdd(&g_tcur[ntype[i]], 1);
        g_perm[p] = i;
    }
}

// ---------------- fused conv GEMM (mma.sync fp16, full tiles) ----------------
// CTA owns 128 dst rows. Loops r = 0..8 (8 relations + root):
//   A_r[row] = sum over edges (r,dst=row) of y1[src]   (root: A = y1[row])
//   acc += A_r @ W_r^T   accumulated in fp32 registers across all 9 passes.
// Epilogue: x1[row] = x[row] + acc[row].
// SMEM: As[128][136] half (A tile), Bs[128][136] half (B^T: Bs[n][k] = W[k][n]).
#define AHS 136
#define GEMM_SMEM (2 * 128 * AHS * 2)   // 69632 bytes

__global__ __launch_bounds__(256, 2)
void conv_gemm_kernel(const float* __restrict__ x,
                      const float* __restrict__ W_rel,
                      const float* __restrict__ W_root,
                      int N) {
    extern __shared__ __half smh[];
    __half (*As)[AHS] = (__half (*)[AHS])smh;
    __half (*Bs)[AHS] = (__half (*)[AHS])(smh + 128 * AHS);

    const int tid  = threadIdx.x;
    const int wid  = tid >> 5;
    const int wm   = wid & 3;      // warp grid 4 (M) x 2 (N): warp tile 32x64
    const int wn   = wid >> 2;
    const int lane = tid & 31;
    const int g    = lane >> 2;    // 0..7
    const int q    = lane & 3;     // 0..3
    const int m0   = blockIdx.x * 128;

    // A stage mapping: row = pass*64 + (tid>>2), 32 cols at (tid&3)*32
    const int grow = tid >> 2;
    const int part = tid & 3;
    // B stage mapping: k = tid>>1, 64 cols at (tid&1)*64
    const int bk  = tid >> 1;
    const int bn0 = (tid & 1) * 64;

    float acc[2][8][4];
    #pragma unroll
    for (int mt = 0; mt < 2; mt++)
        #pragma unroll
        for (int nt = 0; nt < 8; nt++)
            #pragma unroll
            for (int rr = 0; rr < 4; rr++) acc[mt][nt][rr] = 0.0f;

    for (int r = 0; r < 9; r++) {
        // ---- stage A: gathered + summed rows of y1 (fp32 acc -> fp16) ----
        #pragma unroll 1
        for (int pass = 0; pass < 2; pass++) {
            const int row = pass * 64 + grow;
            const int m = m0 + row;
            if (m < N && r == 8) {
                // root pass: direct copy of y1 row (already fp16)
                const uint4* yr = (const uint4*)(g_yh + (size_t)m * DD + part * 32);
                #pragma unroll
                for (int j = 0; j < 4; j++)
                    *(uint4*)&As[row][part * 32 + j * 8] = yr[j];
            } else {
                float f[32];
                #pragma unroll
                for (int j = 0; j < 32; j++) f[j] = 0.0f;
                if (m < N) {
                    const int key = r * N + m;
                    const int beg = g_off2[key], end = g_off2[key + 1];
                    for (int p = beg; p < end; p++) {
                        const int s = g_esrc[p];
                        const uint4* yr = (const uint4*)(g_yh + (size_t)s * DD + part * 32);
                        #pragma unroll
                        for (int j = 0; j < 4; j++) {
                            uint4 u = yr[j];
                            float2 v0 = unp2(u.x), v1 = unp2(u.y);
                            float2 v2 = unp2(u.z), v3 = unp2(u.w);
                            f[j*8+0] += v0.x; f[j*8+1] += v0.y;
                            f[j*8+2] += v1.x; f[j*8+3] += v1.y;
                            f[j*8+4] += v2.x; f[j*8+5] += v2.y;
                            f[j*8+6] += v3.x; f[j*8+7] += v3.y;
                        }
                    }
                }
                #pragma unroll
                for (int j = 0; j < 4; j++) {
                    uint4 u;
                    u.x = pack2(f[j*8+0], f[j*8+1]);
                    u.y = pack2(f[j*8+2], f[j*8+3]);
                    u.z = pack2(f[j*8+4], f[j*8+5]);
                    u.w = pack2(f[j*8+6], f[j*8+7]);
                    *(uint4*)&As[row][part * 32 + j * 8] = u;
                }
            }
        }

        // ---- stage B: Bs[n][k] = W[k][n] (transpose + fp16) ----
        const float* W = (r < 8) ? (W_rel + (size_t)r * DD * DD) : W_root;
        {
            const float4* wr = (const float4*)(W + (size_t)bk * DD + bn0);
            #pragma unroll
            for (int j = 0; j < 16; j++) {
                float4 v = wr[j];
                const int n = bn0 + j * 4;
                Bs[n + 0][bk] = __float2half_rn(v.x);
                Bs[n + 1][bk] = __float2half_rn(v.y);
                Bs[n + 2][bk] = __float2half_rn(v.z);
                Bs[n + 3][bk] = __float2half_rn(v.w);
            }
        }
        __syncthreads();

        // ---- MMA sweep: K=128 in 8 steps of k16, no syncs inside ----
        #pragma unroll
        for (int ks = 0; ks < 8; ks++) {
            const int k0 = ks * 16;
            uint32_t af[2][4];
            #pragma unroll
            for (int mt = 0; mt < 2; mt++) {
                const int r0 = wm * 32 + mt * 16 + g;
                af[mt][0] = *(const uint32_t*)&As[r0    ][k0 + 2*q];
                af[mt][1] = *(const uint32_t*)&As[r0 + 8][k0 + 2*q];
                af[mt][2] = *(const uint32_t*)&As[r0    ][k0 + 2*q + 8];
                af[mt][3] = *(const uint32_t*)&As[r0 + 8][k0 + 2*q + 8];
            }
            uint32_t bf[8][2];
            #pragma unroll
            for (int nt = 0; nt < 8; nt++) {
                const int cn = wn * 64 + nt * 8 + g;
                bf[nt][0] = *(const uint32_t*)&Bs[cn][k0 + 2*q];
                bf[nt][1] = *(const uint32_t*)&Bs[cn][k0 + 2*q + 8];
            }
            #pragma unroll
            for (int mt = 0; mt < 2; mt++)
                #pragma unroll
                for (int nt = 0; nt < 8; nt++)
                    mma_f16(acc[mt][nt][0], acc[mt][nt][1], acc[mt][nt][2], acc[mt][nt][3],
                            af[mt][0], af[mt][1], af[mt][2], af[mt][3],
                            bf[nt][0], bf[nt][1]);
        }
        __syncthreads();
    }

    // epilogue: x1 = x + acc
    #pragma unroll
    for (int mt = 0; mt < 2; mt++) {
        #pragma unroll
        for (int half8 = 0; half8 < 2; half8++) {
            const int rl = wm * 32 + mt * 16 + half8 * 8 + g;
            const int m  = m0 + rl;
            if (m >= N) continue;
            const size_t base = (size_t)m * DD;
            #pragma unroll
            for (int nt = 0; nt < 8; nt++) {
                const int col = wn * 64 + nt * 8 + q * 2;
                float2 ad = *(const float2*)&x[base + col];
                float2 o;
                o.x = acc[mt][nt][half8 * 2 + 0] + ad.x;
                o.y = acc[mt][nt][half8 * 2 + 1] + ad.y;
                *(float2*)&g_x1[base + col] = o;
            }
        }
    }
}

// ---------------- MLP GEMM (mma.sync fp16, type-bucketed) ----------------
// out[perm_row] = x1[perm_row] + b_mlp[t] + y2[perm_row] @ W_mlp[t]
__global__ __launch_bounds__(256, 2)
void mlp_gemm_kernel(const float* __restrict__ W_mlp,
                     const float* __restrict__ biasp,
                     float* __restrict__ out,
                     int N) {
    extern __shared__ __half smh[];
    __half (*As)[AHS] = (__half (*)[AHS])smh;
    __half (*Bs)[AHS] = (__half (*)[AHS])(smh + 128 * AHS);

    const int tid = threadIdx.x;
    const int ty  = blockIdx.y;
    const int Mloc = g_tcnt[ty];
    const int m0 = blockIdx.x * 128;
    if (m0 >= Mloc) return;
    const int* perm = g_perm + g_toff[ty];
    const float* W = W_mlp + (size_t)ty * DD * DD;
    const float* bias = biasp + (size_t)ty * DD;

    const int wid  = tid >> 5;
    const int wm   = wid & 3;
    const int wn   = wid >> 2;
    const int lane = tid & 31;
    const int g    = lane >> 2;
    const int q    = lane & 3;

    const int grow = tid >> 2;
    const int part = tid & 3;
    const int bk  = tid >> 1;
    const int bn0 = (tid & 1) * 64;

    // stage A: y2 rows via perm (direct fp16 copy)
    #pragma unroll 1
    for (int pass = 0; pass < 2; pass++) {
        const int row = pass * 64 + grow;
        const int gr = m0 + row;
        if (gr < Mloc) {
            const int arow = perm[gr];
            const uint4* yr = (const uint4*)(g_yh + (size_t)arow * DD + part * 32);
            #pragma unroll
            for (int j = 0; j < 4; j++)
                *(uint4*)&As[row][part * 32 + j * 8] = yr[j];
        } else {
            const uint4 z = make_uint4(0, 0, 0, 0);
            #pragma unroll
            for (int j = 0; j < 4; j++)
                *(uint4*)&As[row][part * 32 + j * 8] = z;
        }
    }
    // stage B: transpose W
    {
        const float4* wr = (const float4*)(W + (size_t)bk * DD + bn0);
        #pragma unroll
        for (int j = 0; j < 16; j++) {
            float4 v = wr[j];
            const int n = bn0 + j * 4;
            Bs[n + 0][bk] = __float2half_rn(v.x);
            Bs[n + 1][bk] = __float2half_rn(v.y);
            Bs[n + 2][bk] = __float2half_rn(v.z);
            Bs[n + 3][bk] = __float2half_rn(v.w);
        }
    }
    __syncthreads();

    float acc[2][8][4];
    #pragma unroll
    for (int mt = 0; mt < 2; mt++)
        #pragma unroll
        for (int nt = 0; nt < 8; nt++)
            #pragma unroll
            for (int rr = 0; rr < 4; rr++) acc[mt][nt][rr] = 0.0f;

    #pragma unroll
    for (int ks = 0; ks < 8; ks++) {
        const int k0 = ks * 16;
        uint32_t af[2][4];
        #pragma unroll
        for (int mt = 0; mt < 2; mt++) {
            const int r0 = wm * 32 + mt * 16 + g;
            af[mt][0] = *(const uint32_t*)&As[r0    ][k0 + 2*q];
            af[mt][1] = *(const uint32_t*)&As[r0 + 8][k0 + 2*q];
            af[mt][2] = *(const uint32_t*)&As[r0    ][k0 + 2*q + 8];
            af[mt][3] = *(const uint32_t*)&As[r0 + 8][k0 + 2*q + 8];
        }
        uint32_t bf[8][2];
        #pragma unroll
        for (int nt = 0; nt < 8; nt++) {
            const int cn = wn * 64 + nt * 8 + g;
            bf[nt][0] = *(const uint32_t*)&Bs[cn][k0 + 2*q];
            bf[nt][1] = *(const uint32_t*)&Bs[cn][k0 + 2*q + 8];
        }
        #pragma unroll
        for (int mt = 0; mt < 2; mt++)
            #pragma unroll
            for (int nt = 0; nt < 8; nt++)
                mma_f16(acc[mt][nt][0], acc[mt][nt][1], acc[mt][nt][2], acc[mt][nt][3],
                        af[mt][0], af[mt][1], af[mt][2], af[mt][3],
                        bf[nt][0], bf[nt][1]);
    }

    #pragma unroll
    for (int mt = 0; mt < 2; mt++) {
        #pragma unroll
        for (int half8 = 0; half8 < 2; half8++) {
            const int rl  = wm * 32 + mt * 16 + half8 * 8 + g;
            const int grr = m0 + rl;
            if (grr >= Mloc) continue;
            const int prow = perm[grr];
            const size_t base = (size_t)prow * DD;
            #pragma unroll
            for (int nt = 0; nt < 8; nt++) {
                const int col = wn * 64 + nt * 8 + q * 2;
                float2 ad = *(const float2*)&g_x1[base + col];
                float2 bb = *(const float2*)&bias[col];
                float2 o;
                o.x = acc[mt][nt][half8 * 2 + 0] + ad.x + bb.x;
                o.y = acc[mt][nt][half8 * 2 + 1] + ad.y + bb.y;
                *(float2*)&out[base + col] = o;
            }
        }
    }
}

// ---------------- host launcher ----------------
extern "C" void kernel_launch(void* const* d_in, const int* in_sizes, int n_in,
                              void* d_out, int out_size) {
    const float* x          = (const float*)d_in[0];
    const int*   edge_src   = (const int*)  d_in[1];
    const int*   edge_dst   = (const int*)  d_in[2];
    const int*   node_type  = (const int*)  d_in[3];
    const int*   edge_type  = (const int*)  d_in[4];
    const float* conv_gamma = (const float*)d_in[5];
    const float* conv_beta  = (const float*)d_in[6];
    const float* W_rel      = (const float*)d_in[7];
    const float* W_root     = (const float*)d_in[8];
    const float* mlp_gamma  = (const float*)d_in[9];
    const float* mlp_beta   = (const float*)d_in[10];
    const float* W_mlp      = (const float*)d_in[11];
    const float* b_mlp      = (const float*)d_in[12];
    float* out = (float*)d_out;

    const int N  = in_sizes[0] / DD;
    const int E  = in_sizes[1];
    const int N2 = RR * N;

    static int attr_done = 0;
    if (!attr_done) {
        cudaFuncSetAttribute(conv_gemm_kernel,
                             cudaFuncAttributeMaxDynamicSharedMemorySize, GEMM_SMEM);
        cudaFuncSetAttribute(mlp_gemm_kernel,
                             cudaFuncAttributeMaxDynamicSharedMemorySize, GEMM_SMEM);
        attr_done = 1;
    }

    const int THR = 256;
    dim3 blk(THR);
    const int nb = (N2 + SCH - 1) / SCH;
    const int gx = (N + 127) / 128;

    zero_kernel<<<(N2 + THR - 1) / THR, blk>>>(N2);
    ln_relu_kernel<<<(N + 7) / 8, blk>>>(x, node_type, conv_gamma, conv_beta, N, 0, 1);
    count_kernel<<<(E + THR - 1) / THR, blk>>>(edge_dst, edge_type, E, N);
    scan1_kernel<<<nb, blk>>>(N2);
    scan2_kernel<<<1, blk>>>(nb, N2, E);
    scan3_kernel<<<nb, blk>>>(N2);
    scatter_edges_kernel<<<(E + THR - 1) / THR, blk>>>(edge_src, edge_dst, edge_type, E, N);
    scatter_perm_kernel<<<(N + THR - 1) / THR, blk>>>(node_type, N);

    // fused conv: x1 = x + sum_r Z_r @ W_r + y1 @ W_root  (gather + fp16 mma)
    conv_gemm_kernel<<<gx, blk, GEMM_SMEM>>>(x, W_rel, W_root, N);

    ln_relu_kernel<<<(N + 7) / 8, blk>>>(x, node_type, mlp_gamma, mlp_beta, N, 1, 0);

    // MLP: out = x1 + y2 @ W_mlp[type] + b_mlp[type]  (type-bucketed, fp16 mma)
    mlp_gemm_kernel<<<dim3(gx, TTY), blk, GEMM_SMEM>>>(W_mlp, b_mlp, out, N);
}

// round 10
// speedup vs baseline: 1.9951x; 1.0124x over previous
#include <cuda_runtime.h>
#include <cuda_fp16.h>
#include <cstdint>

// Problem constants (shapes fixed by setup_inputs)
#define NMAX 50000
#define EMAX 800000
#define DD   128
#define RR   8
#define TTY  4
#define N2MAX (RR * NMAX)
#define SCH   2048

// ---------------- device scratch (no allocations allowed) ----------------
__device__ __half g_yh[(size_t)NMAX * DD];          // y1 then y2, fp16 (12.8MB, L2-resident)
__device__ float  g_x1[(size_t)NMAX * DD];          // x after conv residual
__device__ int    g_deg2[N2MAX + 1];                // histogram over key=(r*N+dst)
__device__ int    g_off2[N2MAX + 1];
__device__ int    g_cur2[N2MAX];
__device__ int    g_esrc[EMAX];                     // src ids sorted by (r,dst)
__device__ int    g_tcnt[TTY], g_toff[TTY], g_tcur[TTY];
__device__ int    g_perm[NMAX];                     // node ids grouped by type
__device__ int    g_bsum[256];                      // scan block partials

// ---------------- helpers ----------------
__device__ __forceinline__ uint32_t pack2(float a, float b) {
    __half2 h = __floats2half2_rn(a, b);
    return *(uint32_t*)&h;
}
__device__ __forceinline__ float2 unp2(uint32_t w) {
    __half2 h = *(__half2*)&w;
    return __half22float2(h);
}
__device__ __forceinline__ uint32_t smem_u32(const void* p) {
    uint32_t a;
    asm("{ .reg .u64 t; cvta.to.shared.u64 t, %1; cvt.u32.u64 %0, t; }"
        : "=r"(a) : "l"(p));
    return a;
}

__device__ __forceinline__ void mma_f16(float* c,
                                        const uint32_t* a,
                                        uint32_t b0, uint32_t b1) {
    asm volatile(
        "mma.sync.aligned.m16n8k16.row.col.f32.f16.f16.f32 "
        "{%0,%1,%2,%3}, {%4,%5,%6,%7}, {%8,%9}, {%0,%1,%2,%3};\n"
        : "+f"(c[0]), "+f"(c[1]), "+f"(c[2]), "+f"(c[3])
        : "r"(a[0]), "r"(a[1]), "r"(a[2]), "r"(a[3]), "r"(b0), "r"(b1));
}

__device__ __forceinline__ void ldmx4(uint32_t* r, uint32_t addr) {
    asm volatile("ldmatrix.sync.aligned.m8n8.x4.shared.b16 {%0,%1,%2,%3}, [%4];"
        : "=r"(r[0]), "=r"(r[1]), "=r"(r[2]), "=r"(r[3]) : "r"(addr));
}
__device__ __forceinline__ void ldmx4t(uint32_t* r, uint32_t addr) {
    asm volatile("ldmatrix.sync.aligned.m8n8.x4.trans.shared.b16 {%0,%1,%2,%3}, [%4];"
        : "=r"(r[0]), "=r"(r[1]), "=r"(r[2]), "=r"(r[3]) : "r"(addr));
}

// ---------------- small kernels ----------------

__global__ void zero_kernel(int N2) {
    int i = blockIdx.x * blockDim.x + threadIdx.x;
    if (i < N2) g_deg2[i] = 0;
    if (i < TTY) g_tcnt[i] = 0;
}

// LayerNorm (per-node-type affine) + ReLU -> fp16. One warp per node.
__global__ void ln_relu_kernel(const float* __restrict__ xin,
                               const int*   __restrict__ ntype,
                               const float* __restrict__ gamma,
                               const float* __restrict__ beta,
                               int N, int use_internal, int count_types) {
    int gwarp = (blockIdx.x * blockDim.x + threadIdx.x) >> 5;
    int lane  = threadIdx.x & 31;
    if (gwarp >= N) return;
    const float* src = use_internal ? g_x1 : xin;
    float4 v = ((const float4*)(src + (size_t)gwarp * DD))[lane];
    float s  = v.x + v.y + v.z + v.w;
    float sq = v.x*v.x + v.y*v.y + v.z*v.z + v.w*v.w;
    #pragma unroll
    for (int d = 16; d; d >>= 1) {
        s  += __shfl_xor_sync(0xFFFFFFFFu, s,  d);
        sq += __shfl_xor_sync(0xFFFFFFFFu, sq, d);
    }
    float mu  = s * (1.0f / DD);
    float var = sq * (1.0f / DD) - mu * mu;
    float rs  = rsqrtf(var + 1e-5f);
    int t = ntype[gwarp];
    float4 g = ((const float4*)(gamma + (size_t)t * DD))[lane];
    float4 b = ((const float4*)(beta  + (size_t)t * DD))[lane];
    float o0 = fmaxf((v.x - mu) * rs * g.x + b.x, 0.0f);
    float o1 = fmaxf((v.y - mu) * rs * g.y + b.y, 0.0f);
    float o2 = fmaxf((v.z - mu) * rs * g.z + b.z, 0.0f);
    float o3 = fmaxf((v.w - mu) * rs * g.w + b.w, 0.0f);
    uint2 pw;
    pw.x = pack2(o0, o1);
    pw.y = pack2(o2, o3);
    ((uint2*)(g_yh + (size_t)gwarp * DD))[lane] = pw;
    if (count_types && lane == 0) atomicAdd(&g_tcnt[t], 1);
}

__global__ void count_kernel(const int* __restrict__ edst,
                             const int* __restrict__ etype, int E, int N) {
    int i = blockIdx.x * blockDim.x + threadIdx.x;
    if (i < E) atomicAdd(&g_deg2[etype[i] * N + edst[i]], 1);
}

// ---- 3-phase parallel exclusive scan over N2 = R*N bins ----
__global__ void scan1_kernel(int NT) {
    int b = blockIdx.x, t = threadIdx.x;
    int base = b * SCH + t * 8;
    int s = 0;
    #pragma unroll
    for (int i = 0; i < 8; i++) { int idx = base + i; if (idx < NT) s += g_deg2[idx]; }
    #pragma unroll
    for (int d = 16; d; d >>= 1) s += __shfl_xor_sync(0xFFFFFFFFu, s, d);
    __shared__ int red[8];
    if ((t & 31) == 0) red[t >> 5] = s;
    __syncthreads();
    if (t == 0) {
        int tot = 0;
        #pragma unroll
        for (int w = 0; w < 8; w++) tot += red[w];
        g_bsum[b] = tot;
    }
}

__global__ void scan2_kernel(int nb, int NT, int E) {
    int t = threadIdx.x;
    int v = (t < nb) ? g_bsum[t] : 0;
    int x = v;
    #pragma unroll
    for (int d = 1; d < 32; d <<= 1) {
        int n = __shfl_up_sync(0xFFFFFFFFu, x, d);
        if ((t & 31) >= d) x += n;
    }
    __shared__ int ws[8];
    if ((t & 31) == 31) ws[t >> 5] = x;
    __syncthreads();
    if (t == 0) {
        int r = 0;
        #pragma unroll
        for (int w = 0; w < 8; w++) { int y = ws[w]; ws[w] = r; r += y; }
    }
    __syncthreads();
    int incl = x + ws[t >> 5];
    if (t < nb) g_bsum[t] = incl - v;
    if (t == 0) {
        g_off2[NT] = E;
        int r = 0;
        #pragma unroll
        for (int tt = 0; tt < TTY; tt++) {
            g_toff[tt] = r; g_tcur[tt] = r; r += g_tcnt[tt];
        }
    }
}

__global__ void scan3_kernel(int NT) {
    int b = blockIdx.x, t = threadIdx.x;
    int base = b * SCH + t * 8;
    int v[8]; int s = 0;
    #pragma unroll
    for (int i = 0; i < 8; i++) {
        int idx = base + i;
        v[i] = (idx < NT) ? g_deg2[idx] : 0;
        s += v[i];
    }
    int x = s;
    #pragma unroll
    for (int d = 1; d < 32; d <<= 1) {
        int n = __shfl_up_sync(0xFFFFFFFFu, x, d);
        if ((t & 31) >= d) x += n;
    }
    __shared__ int ws[8];
    if ((t & 31) == 31) ws[t >> 5] = x;
    __syncthreads();
    if (t == 0) {
        int r = 0;
        #pragma unroll
        for (int w = 0; w < 8; w++) { int y = ws[w]; ws[w] = r; r += y; }
    }
    __syncthreads();
    int run = g_bsum[b] + (x + ws[t >> 5]) - s;
    #pragma unroll
    for (int i = 0; i < 8; i++) {
        int idx = base + i;
        if (idx < NT) { g_off2[idx] = run; g_cur2[idx] = run; run += v[i]; }
    }
}

__global__ void scatter_edges_kernel(const int* __restrict__ esrc,
                                     const int* __restrict__ edst,
                                     const int* __restrict__ etype, int E, int N) {
    int i = blockIdx.x * blockDim.x + threadIdx.x;
    if (i < E) {
        int key = etype[i] * N + edst[i];
        int p = atomicAdd(&g_cur2[key], 1);
        g_esrc[p] = esrc[i];
    }
}

__global__ void scatter_perm_kernel(const int* __restrict__ ntype, int N) {
    int i = blockIdx.x * blockDim.x + threadIdx.x;
    if (i < N) {
        int p = atomicAdd(&g_tcur[ntype[i]], 1);
        g_perm[p] = i;
    }
}

// ---------------- GEMM geometry ----------------
// M-tile 96, N=K=128. 256 threads, warp grid 2(M)x4(N), warp tile 48x32.
// As[96][136] row-major (m,k) fp16; Bs[128][136] row-major (k,n) fp16.
// Fragments via ldmatrix (A) / ldmatrix.trans (B).
#define AHS   136
#define AROWS 96
#define GEMM_SMEM ((AROWS + 128) * AHS * 2)   // 60928 bytes

// ---------------- fused conv GEMM ----------------
// CTA owns 96 dst rows. Loops r = 0..8 (8 relations + root):
//   A_r[row] = sum over edges (r,dst=row) of y1[src]   (root: A = y1[row])
//   acc += A_r @ W_r^T   accumulated in fp32 registers across all 9 passes.
// Epilogue: x1[row] = x[row] + acc[row].
__global__ __launch_bounds__(256, 2)
void conv_gemm_kernel(const float* __restrict__ x,
                      const float* __restrict__ W_rel,
                      const float* __restrict__ W_root,
                      int N) {
    extern __shared__ __half smh[];
    __half (*As)[AHS] = (__half (*)[AHS])smh;
    __half (*Bs)[AHS] = (__half (*)[AHS])(smh + AROWS * AHS);

    const int tid  = threadIdx.x;
    const int wid  = tid >> 5;
    const int wm   = wid & 1;      // 2 M groups x 48 rows
    const int wn   = wid >> 1;     // 4 N groups x 32 cols
    const int lane = tid & 31;
    const int g    = lane >> 2;
    const int q    = lane & 3;
    const int m0   = blockIdx.x * AROWS;

    // staging maps
    const int grow = tid >> 2;            // A row (0..63) per pass
    const int part = tid & 3;             // A col quarter (32 halves)
    const int bk   = tid >> 1;            // B k-row (0..127)
    const int bn0  = (tid & 1) * 64;      // B n-half

    // fragment load addresses (lane-invariant parts precomputed)
    const uint32_t as_b = smem_u32(As);
    const uint32_t bs_b = smem_u32(Bs);
    uint32_t aaddr[3];
    #pragma unroll
    for (int mt = 0; mt < 3; mt++)
        aaddr[mt] = as_b + (uint32_t)(wm * 48 + mt * 16 + (lane & 15)) * (AHS * 2)
                         + (uint32_t)((lane >> 4) * 8) * 2;
    uint32_t baddr[2];
    #pragma unroll
    for (int grp = 0; grp < 2; grp++)
        baddr[grp] = bs_b + (uint32_t)((lane & 7) + ((lane >> 3) & 1) * 8) * (AHS * 2)
                          + (uint32_t)(wn * 32 + grp * 16 + (lane >> 4) * 8) * 2;

    float acc[3][4][4];
    #pragma unroll
    for (int mt = 0; mt < 3; mt++)
        #pragma unroll
        for (int nt = 0; nt < 4; nt++)
            #pragma unroll
            for (int rr = 0; rr < 4; rr++) acc[mt][nt][rr] = 0.0f;

    for (int r = 0; r < 9; r++) {
        // ---- stage A: gathered + summed rows of y1 ----
        #pragma unroll 1
        for (int pass = 0; pass < 2; pass++) {
            const int row = pass * 64 + grow;
            if (row < AROWS) {
                const int m = m0 + row;
                if (m < N && r == 8) {
                    const uint4* yr = (const uint4*)(g_yh + (size_t)m * DD + part * 32);
                    #pragma unroll
                    for (int j = 0; j < 4; j++)
                        *(uint4*)&As[row][part * 32 + j * 8] = yr[j];
                } else {
                    float f[32];
                    #pragma unroll
                    for (int j = 0; j < 32; j++) f[j] = 0.0f;
                    if (m < N) {
                        const int key = r * N + m;
                        const int beg = g_off2[key], end = g_off2[key + 1];
                        for (int p = beg; p < end; p++) {
                            const int s = g_esrc[p];
                            const uint4* yr = (const uint4*)(g_yh + (size_t)s * DD + part * 32);
                            #pragma unroll
                            for (int j = 0; j < 4; j++) {
                                uint4 u = yr[j];
                                float2 v0 = unp2(u.x), v1 = unp2(u.y);
                                float2 v2 = unp2(u.z), v3 = unp2(u.w);
                                f[j*8+0] += v0.x; f[j*8+1] += v0.y;
                                f[j*8+2] += v1.x; f[j*8+3] += v1.y;
                                f[j*8+4] += v2.x; f[j*8+5] += v2.y;
                                f[j*8+6] += v3.x; f[j*8+7] += v3.y;
                            }
                        }
                    }
                    #pragma unroll
                    for (int j = 0; j < 4; j++) {
                        uint4 u;
                        u.x = pack2(f[j*8+0], f[j*8+1]);
                        u.y = pack2(f[j*8+2], f[j*8+3]);
                        u.z = pack2(f[j*8+4], f[j*8+5]);
                        u.w = pack2(f[j*8+6], f[j*8+7]);
                        *(uint4*)&As[row][part * 32 + j * 8] = u;
                    }
                }
            }
        }

        // ---- stage B: Bs[k][n] = W[k][n] (row-major, coalesced) ----
        const float* W = (r < 8) ? (W_rel + (size_t)r * DD * DD) : W_root;
        {
            const float4* wr = (const float4*)(W + (size_t)bk * DD + bn0);
            #pragma unroll
            for (int jj = 0; jj < 8; jj++) {
                float4 v0 = wr[2 * jj];
                float4 v1 = wr[2 * jj + 1];
                uint4 u;
                u.x = pack2(v0.x, v0.y);
                u.y = pack2(v0.z, v0.w);
                u.z = pack2(v1.x, v1.y);
                u.w = pack2(v1.z, v1.w);
                *(uint4*)&Bs[bk][bn0 + jj * 8] = u;
            }
        }
        __syncthreads();

        // ---- MMA sweep: K=128 in 8 steps of k16 ----
        #pragma unroll
        for (int ks = 0; ks < 8; ks++) {
            uint32_t af[3][4];
            #pragma unroll
            for (int mt = 0; mt < 3; mt++) ldmx4(af[mt], aaddr[mt] + ks * 32);
            uint32_t bf[2][4];
            #pragma unroll
            for (int grp = 0; grp < 2; grp++) ldmx4t(bf[grp], baddr[grp] + ks * 16 * (AHS * 2));
            #pragma unroll
            for (int mt = 0; mt < 3; mt++)
                #pragma unroll
                for (int nt = 0; nt < 4; nt++)
                    mma_f16(acc[mt][nt], af[mt],
                            bf[nt >> 1][(nt & 1) * 2], bf[nt >> 1][(nt & 1) * 2 + 1]);
        }
        __syncthreads();
    }

    // epilogue: x1 = x + acc
    #pragma unroll
    for (int mt = 0; mt < 3; mt++) {
        #pragma unroll
        for (int half8 = 0; half8 < 2; half8++) {
            const int rl = wm * 48 + mt * 16 + half8 * 8 + g;
            const int m  = m0 + rl;
            if (m >= N) continue;
            const size_t base = (size_t)m * DD;
            #pragma unroll
            for (int nt = 0; nt < 4; nt++) {
                const int col = wn * 32 + nt * 8 + q * 2;
                float2 ad = *(const float2*)&x[base + col];
                float2 o;
                o.x = acc[mt][nt][half8 * 2 + 0] + ad.x;
                o.y = acc[mt][nt][half8 * 2 + 1] + ad.y;
                *(float2*)&g_x1[base + col] = o;
            }
        }
    }
}

// ---------------- MLP GEMM (type-bucketed) ----------------
// out[perm_row] = x1[perm_row] + b_mlp[t] + y2[perm_row] @ W_mlp[t]
__global__ __launch_bounds__(256, 2)
void mlp_gemm_kernel(const float* __restrict__ W_mlp,
                     const float* __restrict__ biasp,
                     float* __restrict__ out,
                     int N) {
    const int ty  = blockIdx.y;
    const int Mloc = g_tcnt[ty];
    const int m0 = blockIdx.x * AROWS;
    if (m0 >= Mloc) return;

    extern __shared__ __half smh[];
    __half (*As)[AHS] = (__half (*)[AHS])smh;
    __half (*Bs)[AHS] = (__half (*)[AHS])(smh + AROWS * AHS);

    const int tid  = threadIdx.x;
    const int wid  = tid >> 5;
    const int wm   = wid & 1;
    const int wn   = wid >> 1;
    const int lane = tid & 31;
    const int g    = lane >> 2;
    const int q    = lane & 3;

    const int* perm = g_perm + g_toff[ty];
    const float* W = W_mlp + (size_t)ty * DD * DD;
    const float* bias = biasp + (size_t)ty * DD;

    const int grow = tid >> 2;
    const int part = tid & 3;
    const int bk   = tid >> 1;
    const int bn0  = (tid & 1) * 64;

    const uint32_t as_b = smem_u32(As);
    const uint32_t bs_b = smem_u32(Bs);
    uint32_t aaddr[3];
    #pragma unroll
    for (int mt = 0; mt < 3; mt++)
        aaddr[mt] = as_b + (uint32_t)(wm * 48 + mt * 16 + (lane & 15)) * (AHS * 2)
                         + (uint32_t)((lane >> 4) * 8) * 2;
    uint32_t baddr[2];
    #pragma unroll
    for (int grp = 0; grp < 2; grp++)
        baddr[grp] = bs_b + (uint32_t)((lane & 7) + ((lane >> 3) & 1) * 8) * (AHS * 2)
                          + (uint32_t)(wn * 32 + grp * 16 + (lane >> 4) * 8) * 2;

    // stage A: y2 rows via perm
    #pragma unroll 1
    for (int pass = 0; pass < 2; pass++) {
        const int row = pass * 64 + grow;
        if (row < AROWS) {
            const int gr = m0 + row;
            if (gr < Mloc) {
                const int arow = perm[gr];
                const uint4* yr = (const uint4*)(g_yh + (size_t)arow * DD + part * 32);
                #pragma unroll
                for (int j = 0; j < 4; j++)
                    *(uint4*)&As[row][part * 32 + j * 8] = yr[j];
            } else {
                const uint4 z = make_uint4(0, 0, 0, 0);
                #pragma unroll
                for (int j = 0; j < 4; j++)
                    *(uint4*)&As[row][part * 32 + j * 8] = z;
            }
        }
    }
    // stage B
    {
        const float4* wr = (const float4*)(W + (size_t)bk * DD + bn0);
        #pragma unroll
        for (int jj = 0; jj < 8; jj++) {
            float4 v0 = wr[2 * jj];
            float4 v1 = wr[2 * jj + 1];
            uint4 u;
            u.x = pack2(v0.x, v0.y);
            u.y = pack2(v0.z, v0.w);
            u.z = pack2(v1.x, v1.y);
            u.w = pack2(v1.z, v1.w);
            *(uint4*)&Bs[bk][bn0 + jj * 8] = u;
        }
    }
    __syncthreads();

    float acc[3][4][4];
    #pragma unroll
    for (int mt = 0; mt < 3; mt++)
        #pragma unroll
        for (int nt = 0; nt < 4; nt++)
            #pragma unroll
            for (int rr = 0; rr < 4; rr++) acc[mt][nt][rr] = 0.0f;

    #pragma unroll
    for (int ks = 0; ks < 8; ks++) {
        uint32_t af[3][4];
        #pragma unroll
        for (int mt = 0; mt < 3; mt++) ldmx4(af[mt], aaddr[mt] + ks * 32);
        uint32_t bf[2][4];
        #pragma unroll
        for (int grp = 0; grp < 2; grp++) ldmx4t(bf[grp], baddr[grp] + ks * 16 * (AHS * 2));
        #pragma unroll
        for (int mt = 0; mt < 3; mt++)
            #pragma unroll
            for (int nt = 0; nt < 4; nt++)
                mma_f16(acc[mt][nt], af[mt],
                        bf[nt >> 1][(nt & 1) * 2], bf[nt >> 1][(nt & 1) * 2 + 1]);
    }

    #pragma unroll
    for (int mt = 0; mt < 3; mt++) {
        #pragma unroll
        for (int half8 = 0; half8 < 2; half8++) {
            const int rl  = wm * 48 + mt * 16 + half8 * 8 + g;
            const int grr = m0 + rl;
            if (grr >= Mloc) continue;
            const int prow = perm[grr];
            const size_t base = (size_t)prow * DD;
            #pragma unroll
            for (int nt = 0; nt < 4; nt++) {
                const int col = wn * 32 + nt * 8 + q * 2;
                float2 ad = *(const float2*)&g_x1[base + col];
                float2 bb = *(const float2*)&bias[col];
                float2 o;
                o.x = acc[mt][nt][half8 * 2 + 0] + ad.x + bb.x;
                o.y = acc[mt][nt][half8 * 2 + 1] + ad.y + bb.y;
                *(float2*)&out[base + col] = o;
            }
        }
    }
}

// ---------------- host launcher ----------------
extern "C" void kernel_launch(void* const* d_in, const int* in_sizes, int n_in,
                              void* d_out, int out_size) {
    const float* x          = (const float*)d_in[0];
    const int*   edge_src   = (const int*)  d_in[1];
    const int*   edge_dst   = (const int*)  d_in[2];
    const int*   node_type  = (const int*)  d_in[3];
    const int*   edge_type  = (const int*)  d_in[4];
    const float* conv_gamma = (const float*)d_in[5];
    const float* conv_beta  = (const float*)d_in[6];
    const float* W_rel      = (const float*)d_in[7];
    const float* W_root     = (const float*)d_in[8];
    const float* mlp_gamma  = (const float*)d_in[9];
    const float* mlp_beta   = (const float*)d_in[10];
    const float* W_mlp      = (const float*)d_in[11];
    const float* b_mlp      = (const float*)d_in[12];
    float* out = (float*)d_out;

    const int N  = in_sizes[0] / DD;
    const int E  = in_sizes[1];
    const int N2 = RR * N;

    static int attr_done = 0;
    if (!attr_done) {
        cudaFuncSetAttribute(conv_gemm_kernel,
                             cudaFuncAttributeMaxDynamicSharedMemorySize, GEMM_SMEM);
        cudaFuncSetAttribute(mlp_gemm_kernel,
                             cudaFuncAttributeMaxDynamicSharedMemorySize, GEMM_SMEM);
        attr_done = 1;
    }

    const int THR = 256;
    dim3 blk(THR);
    const int nb = (N2 + SCH - 1) / SCH;
    const int gx = (N + AROWS - 1) / AROWS;

    zero_kernel<<<(N2 + THR - 1) / THR, blk>>>(N2);
    ln_relu_kernel<<<(N + 7) / 8, blk>>>(x, node_type, conv_gamma, conv_beta, N, 0, 1);
    count_kernel<<<(E + THR - 1) / THR, blk>>>(edge_dst, edge_type, E, N);
    scan1_kernel<<<nb, blk>>>(N2);
    scan2_kernel<<<1, blk>>>(nb, N2, E);
    scan3_kernel<<<nb, blk>>>(N2);
    scatter_edges_kernel<<<(E + THR - 1) / THR, blk>>>(edge_src, edge_dst, edge_type, E, N);
    scatter_perm_kernel<<<(N + THR - 1) / THR, blk>>>(node_type, N);

    // fused conv: x1 = x + sum_r Z_r @ W_r + y1 @ W_root  (gather + fp16 mma)
    conv_gemm_kernel<<<gx, blk, GEMM_SMEM>>>(x, W_rel, W_root, N);

    ln_relu_kernel<<<(N + 7) / 8, blk>>>(x, node_type, mlp_gamma, mlp_beta, N, 1, 0);

    // MLP: out = x1 + y2 @ W_mlp[type] + b_mlp[type]  (type-bucketed, fp16 mma)
    mlp_gemm_kernel<<<dim3(gx, TTY), blk, GEMM_SMEM>>>(W_mlp, b_mlp, out, N);
}